// round 7
// baseline (speedup 1.0000x reference)
#include <cuda_runtime.h>
#include <cuda_bf16.h>
#include <math.h>
#include <stdint.h>

#define VNUM   5023
#define NJ     5
#define NB     1024
#define NSHAPE 100
#define NEXPR  50
#define NBETA  150
#define NLMK   68
#define NPOSE  36
#define JR_COLS 453
#define PD_N   (VNUM * 3)      // 15069

#define KP    192              // padded K: 150 betas + 36 pose feats + 6 zero
#define NPAD4 20096            // 157 * 128 >= 4*VNUM

#define VB      20             // vertices per F1 block
#define F1_BLK  252            // 252*20 = 5040 >= 5024

// ---- device scratch ----
__device__ float g_partial[F1_BLK * NJ * JR_COLS];    // 2.3 MB
__device__ float g_Jr[NJ * JR_COLS];
__device__ float g_relT[NB * NJ * 12];
__device__ __nv_bfloat16 g_A[NB * KP];                // 0.4 MB
__device__ __nv_bfloat16 g_B4[(size_t)NPAD4 * KP];    // 7.7 MB

__device__ __forceinline__ uint32_t smem_u32(const void* p) {
    uint32_t a;
    asm("{ .reg .u64 t; cvta.to.shared.u64 t, %1; cvt.u32.u64 %0, t; }" : "=r"(a) : "l"(p));
    return a;
}

#define LDSM4(R0, R1, R2, R3, ADDR) \
    asm volatile("ldmatrix.sync.aligned.m8n8.x4.shared.b16 {%0,%1,%2,%3}, [%4];" \
        : "=r"(R0), "=r"(R1), "=r"(R2), "=r"(R3) : "r"(ADDR))

#define MMA16816(C, A0, A1, A2, A3, B0, B1) \
    asm volatile("mma.sync.aligned.m16n8k16.row.col.f32.bf16.bf16.f32 " \
        "{%0,%1,%2,%3},{%4,%5,%6,%7},{%8,%9},{%0,%1,%2,%3};" \
        : "+f"((C)[0]), "+f"((C)[1]), "+f"((C)[2]), "+f"((C)[3]) \
        : "r"(A0), "r"(A1), "r"(A2), "r"(A3), "r"(B0), "r"(B1))

#define CP_ASYNC16(DST, SRC) \
    asm volatile("cp.async.cg.shared.global [%0], [%1], 16;" :: "r"(DST), "l"(SRC))
#define CP_ASYNC_WAIT() \
    asm volatile("cp.async.commit_group;\n\tcp.async.wait_group 0;" ::: "memory")

// ============================================================
// Launch 1 — kernF1: fused B4 build + Jr partials.
// 252 blocks x 256 threads; each block owns 20 vertices, processed
// in 2 sub-chunks of 10 (sd rows staged in smem once, used twice).
// ============================================================
__global__ void __launch_bounds__(256) kernF1(
    const float* __restrict__ sd, const float* __restrict__ vt,
    const float* __restrict__ pd, const float* __restrict__ Jreg)
{
    __shared__ float s_sd[10][456];    // 10 rows x (450 sd | 3 vt | pad)
    __shared__ float s_jr[NJ][VB];
    int tid = threadIdx.x;
    int v0 = blockIdx.x * VB;

    for (int i = tid; i < NJ * VB; i += 256) {
        int j = i / VB, vv = i % VB;
        int v = v0 + vv;
        s_jr[j][vv] = (v < VNUM) ? Jreg[j * VNUM + v] : 0.f;
    }

    float acc[10];
#pragma unroll
    for (int q = 0; q < 10; q++) acc[q] = 0.f;
    int col0 = tid, col1 = tid + 256;

    for (int sub = 0; sub < 2; sub++) {
        __syncthreads();
        int vbase = v0 + sub * 10;
        // stage 10 sd rows (+vt) coalesced
        for (int i = tid; i < 10 * 456; i += 256) {
            int r = i / 456, c = i - r * 456;
            int v = vbase + r;
            float val = 0.f;
            if (v < VNUM) {
                if (c < 450)      val = sd[v * 450 + c];
                else if (c < 453) val = vt[v * 3 + (c - 450)];
            }
            s_sd[r][c] = val;
        }
        __syncthreads();

        // Jr partial accumulation
#pragma unroll
        for (int r = 0; r < 10; r++) {
            int vv = sub * 10 + r;
            float j0 = s_jr[0][vv], j1 = s_jr[1][vv], j2 = s_jr[2][vv];
            float j3 = s_jr[3][vv], j4 = s_jr[4][vv];
            float x0 = s_sd[r][col0];
            acc[0] = fmaf(j0, x0, acc[0]); acc[1] = fmaf(j1, x0, acc[1]);
            acc[2] = fmaf(j2, x0, acc[2]); acc[3] = fmaf(j3, x0, acc[3]);
            acc[4] = fmaf(j4, x0, acc[4]);
            if (col1 < JR_COLS) {
                float x1 = s_sd[r][col1];
                acc[5] = fmaf(j0, x1, acc[5]); acc[6] = fmaf(j1, x1, acc[6]);
                acc[7] = fmaf(j2, x1, acc[7]); acc[8] = fmaf(j3, x1, acc[8]);
                acc[9] = fmaf(j4, x1, acc[9]);
            }
        }

        // B4 rows for these 10 vertices (40 rows x 192)
        for (int i = tid; i < 40 * KP; i += 256) {
            int nl = i / KP, k = i - nl * KP;
            int n = vbase * 4 + nl;
            if (n < NPAD4) {
                int vl2 = nl >> 2, c = nl & 3;
                int v = vbase + vl2;
                float val = 0.f;
                if (v < VNUM && c < 3) {
                    if (k < NBETA)              val = s_sd[vl2][c * NBETA + k];
                    else if (k < NBETA + NPOSE) val = pd[(size_t)(k - NBETA) * PD_N + (v * 3 + c)];
                }
                g_B4[(size_t)n * KP + k] = __float2bfloat16(val);
            }
        }
    }

#pragma unroll
    for (int j = 0; j < NJ; j++) {
        g_partial[(blockIdx.x * NJ + j) * JR_COLS + col0] = acc[j];
        if (col1 < JR_COLS)
            g_partial[(blockIdx.x * NJ + j) * JR_COLS + col1] = acc[5 + j];
    }
}

// ============================================================
// Launch 2 — kernA2: reduce 252 partials -> g_Jr.  grid (5,4) x 128
// ============================================================
__global__ void kernA2()
{
    int j = blockIdx.x;
    int col = blockIdx.y * 128 + threadIdx.x;
    if (col >= JR_COLS) return;
    float s = 0.f;
#pragma unroll 6
    for (int ch = 0; ch < F1_BLK; ch++)
        s += g_partial[(ch * NJ + j) * JR_COLS + col];
    g_Jr[j * JR_COLS + col] = s;
}

// ============================================================
// Launch 3 — kernB: joints, Rodrigues, chain -> g_relT + bf16 A rows.
// 32 blocks x 32 threads (1 batch/thread).
// ============================================================
#define BP 153

__global__ void __launch_bounds__(32) kernB(
    const float* __restrict__ shape, const float* __restrict__ expr,
    const float* __restrict__ pose, const float* __restrict__ eye,
    const float* __restrict__ neck)
{
    __shared__ float s_jr[NJ * JR_COLS];
    __shared__ float s_beta[32 * BP];
    int tid = threadIdx.x;
    int b0 = blockIdx.x * 32;

    for (int i = tid; i < NJ * JR_COLS; i += 32) s_jr[i] = g_Jr[i];
    for (int i = tid; i < 32 * NSHAPE; i += 32)
        s_beta[(i / NSHAPE) * BP + (i % NSHAPE)] = shape[b0 * NSHAPE + i];
    for (int i = tid; i < 32 * NEXPR; i += 32)
        s_beta[(i / NEXPR) * BP + NSHAPE + (i % NEXPR)] = expr[b0 * NEXPR + i];
    __syncthreads();

    int b = b0 + tid;
    const float* myb = s_beta + tid * BP;

    float J[NJ][3];
#pragma unroll
    for (int j = 0; j < NJ; j++)
#pragma unroll
        for (int c = 0; c < 3; c++) J[j][c] = s_jr[j * JR_COLS + 450 + c];

    for (int l = 0; l < NBETA; l++) {
        float blv = myb[l];
#pragma unroll
        for (int j = 0; j < NJ; j++)
#pragma unroll
            for (int c = 0; c < 3; c++) J[j][c] = fmaf(s_jr[j * JR_COLS + l], blv, J[j][c]);
    }

    float fp[15];
    fp[0] = pose[b * 6 + 0]; fp[1] = pose[b * 6 + 1]; fp[2] = pose[b * 6 + 2];
    fp[3] = neck[0]; fp[4] = neck[1]; fp[5] = neck[2];
    fp[6] = pose[b * 6 + 3]; fp[7] = pose[b * 6 + 4]; fp[8] = pose[b * 6 + 5];
#pragma unroll
    for (int k = 0; k < 6; k++) fp[9 + k] = eye[k];

    float R[NJ][9];
#pragma unroll
    for (int j = 0; j < NJ; j++) {
        float x = fp[j * 3 + 0], y = fp[j * 3 + 1], z = fp[j * 3 + 2];
        float xa = x + 1e-8f, ya = y + 1e-8f, za = z + 1e-8f;
        float ang = sqrtf(xa * xa + ya * ya + za * za);
        float inv = 1.f / ang;
        float rx = x * inv, ry = y * inv, rz = z * inv;
        float s, c;
        sincosf(ang, &s, &c);
        float t = 1.f - c;
        R[j][0] = 1.f - t * (ry * ry + rz * rz);
        R[j][1] = -s * rz + t * rx * ry;
        R[j][2] =  s * ry + t * rx * rz;
        R[j][3] =  s * rz + t * rx * ry;
        R[j][4] = 1.f - t * (rx * rx + rz * rz);
        R[j][5] = -s * rx + t * ry * rz;
        R[j][6] = -s * ry + t * rx * rz;
        R[j][7] =  s * rx + t * ry * rz;
        R[j][8] = 1.f - t * (rx * rx + ry * ry);
    }

    // --- g_A row: [betas(150) | pose_feature(36) | 0 pad(6)] bf16 ---
    {
        __nv_bfloat16* arow = g_A + (size_t)b * KP;
#pragma unroll 2
        for (int l = 0; l < NBETA; l++) arow[l] = __float2bfloat16(myb[l]);
#pragma unroll
        for (int j = 1; j < NJ; j++)
#pragma unroll
            for (int k = 0; k < 9; k++) {
                float d = (k == 0 || k == 4 || k == 8) ? 1.f : 0.f;
                arow[NBETA + (j - 1) * 9 + k] = __float2bfloat16(R[j][k] - d);
            }
#pragma unroll
        for (int k = NBETA + NPOSE; k < KP; k++) arow[k] = __float2bfloat16(0.f);
    }

    const int par[NJ] = { -1, 0, 1, 1, 1 };
    float rel[NJ][3];
#pragma unroll
    for (int c = 0; c < 3; c++) rel[0][c] = J[0][c];
#pragma unroll
    for (int j = 1; j < NJ; j++)
#pragma unroll
        for (int c = 0; c < 3; c++) rel[j][c] = J[j][c] - J[par[j]][c];

    float cR[NJ][9], ct[NJ][3];
#pragma unroll
    for (int k = 0; k < 9; k++) cR[0][k] = R[0][k];
#pragma unroll
    for (int c = 0; c < 3; c++) ct[0][c] = rel[0][c];
#pragma unroll
    for (int j = 1; j < NJ; j++) {
        int p = par[j];
#pragma unroll
        for (int r = 0; r < 3; r++) {
#pragma unroll
            for (int c = 0; c < 3; c++)
                cR[j][r * 3 + c] = cR[p][r * 3 + 0] * R[j][0 + c]
                                 + cR[p][r * 3 + 1] * R[j][3 + c]
                                 + cR[p][r * 3 + 2] * R[j][6 + c];
            ct[j][r] = cR[p][r * 3 + 0] * rel[j][0] + cR[p][r * 3 + 1] * rel[j][1]
                     + cR[p][r * 3 + 2] * rel[j][2] + ct[p][r];
        }
    }

#pragma unroll
    for (int j = 0; j < NJ; j++)
#pragma unroll
        for (int r = 0; r < 3; r++) {
            float tr = ct[j][r] - (cR[j][r * 3 + 0] * J[j][0] + cR[j][r * 3 + 1] * J[j][1]
                                 + cR[j][r * 3 + 2] * J[j][2]);
            g_relT[b * 60 + j * 12 + r * 4 + 0] = cR[j][r * 3 + 0];
            g_relT[b * 60 + j * 12 + r * 4 + 1] = cR[j][r * 3 + 1];
            g_relT[b * 60 + j * 12 + r * 4 + 2] = cR[j][r * 3 + 2];
            g_relT[b * 60 + j * 12 + r * 4 + 3] = tr;
        }
}

// ============================================================
// Launch 4 — kernG: C[128b x 128n] = A @ B4^T (mma.sync bf16)
// + fused LBS epilogue.  256 thr = 8 warps (4b x 2n), warp tile 32x64.
// K=192 smem-resident, cp.async staging, 2 CTAs/SM.
// smem mainloop: A@0 (128x400B=51200), B@51200 (51200) -> 102400
// epilogue reuse: sC@0 (128x132 f32=67584), relT@67584 (30720),
//                 wvt@98304 (32x8 f32 = 1024)
// Epilogue: thread owns one batch-row (bl = tid&127), relT hoisted to
// registers once, 16 vertices per thread; results staged back into sC
// and written with a final coalesced sweep.
// ============================================================
#define SMB_OFF 51200
#define SM_TOT  102400

__global__ void __launch_bounds__(256, 2) kernG(
    const float* __restrict__ vt, const float* __restrict__ lw,
    float* __restrict__ out)
{
    extern __shared__ char smr[];
    uint32_t sb = smem_u32(smr);
    int tid = threadIdx.x;
    int lane = tid & 31, w = tid >> 5;
    int wm = w & 3, wn = w >> 2;          // 4b x 2n grid, warp tile 32b x 64n
    int n0 = blockIdx.x * 128;
    int b0 = blockIdx.y * 128;
    int v0 = n0 >> 2;                     // 32 vertices per tile

    // --- stage A,B tiles (each 128 x 24 uint4, pitch 400B) via cp.async ---
    {
        const uint4* gA4 = (const uint4*)(g_A + (size_t)b0 * KP);
        const uint4* gB4 = (const uint4*)(g_B4 + (size_t)n0 * KP);
        for (int i = tid; i < 128 * 24; i += 256) {
            int row = i / 24, q = i - row * 24;
            CP_ASYNC16(sb + row * 400 + q * 16, gA4 + i);
            CP_ASYNC16(sb + SMB_OFF + row * 400 + q * 16, gB4 + i);
        }
        CP_ASYNC_WAIT();
    }
    __syncthreads();

    float acc[2][8][4];
#pragma unroll
    for (int a = 0; a < 2; a++)
#pragma unroll
        for (int j = 0; j < 8; j++)
#pragma unroll
            for (int k = 0; k < 4; k++) acc[a][j][k] = 0.f;

    int lrow = lane & 15;
    uint32_t koff = (uint32_t)((lane >> 4) * 16);
    uint32_t aBase = sb + (wm * 32 + lrow) * 400 + koff;
    uint32_t bBase = sb + SMB_OFF + (wn * 64 + lrow) * 400 + koff;

#pragma unroll
    for (int ks = 0; ks < 12; ks++) {
        uint32_t kb = (uint32_t)ks * 32u;
        uint32_t ra[2][4], rb[4][4];
        LDSM4(ra[0][0], ra[0][1], ra[0][2], ra[0][3], aBase + kb);
        LDSM4(ra[1][0], ra[1][1], ra[1][2], ra[1][3], aBase + 16 * 400 + kb);
#pragma unroll
        for (int jj = 0; jj < 4; jj++)
            LDSM4(rb[jj][0], rb[jj][1], rb[jj][2], rb[jj][3], bBase + jj * (16 * 400) + kb);
#pragma unroll
        for (int a = 0; a < 2; a++)
#pragma unroll
            for (int jj = 0; jj < 4; jj++) {
                MMA16816(acc[a][jj * 2],     ra[a][0], ra[a][1], ra[a][2], ra[a][3],
                         rb[jj][0], rb[jj][2]);
                MMA16816(acc[a][jj * 2 + 1], ra[a][0], ra[a][1], ra[a][2], ra[a][3],
                         rb[jj][1], rb[jj][3]);
            }
    }

    __syncthreads();   // done reading A/B smem

    // --- write accumulators to sC [128 x 132] f32 ---
    float* sC = (float*)smr;
#pragma unroll
    for (int a = 0; a < 2; a++) {
        int r = wm * 32 + a * 16 + (lane >> 2);
        int cb = wn * 64 + (lane & 3) * 2;
#pragma unroll
        for (int j = 0; j < 8; j++) {
            int c = cb + j * 8;
            sC[r * 132 + c]           = acc[a][j][0];
            sC[r * 132 + c + 1]       = acc[a][j][1];
            sC[(r + 8) * 132 + c]     = acc[a][j][2];
            sC[(r + 8) * 132 + c + 1] = acc[a][j][3];
        }
    }

    // --- stage relT (128x60) and packed weights+template (32x8) ---
    float* sRT = (float*)(smr + 67584);
    for (int i = tid; i < 128 * 60; i += 256) sRT[i] = g_relT[b0 * 60 + i];
    float* sWVT = (float*)(smr + 98304);
    for (int i = tid; i < 32 * 8; i += 256) {
        int vl = i >> 3, q = i & 7;
        int v = v0 + vl;
        float val = 0.f;
        if (v < VNUM) {
            if (q < 5)      val = lw[v * NJ + q];
            else if (q < 8) val = vt[v * 3 + (q - 5)];
        }
        sWVT[i] = val;
    }
    __syncthreads();

    // --- epilogue: thread owns bl; relT in registers; 16 v each ---
    {
        int bl = tid & 127;
        int half = tid >> 7;
        const float4* rtp = (const float4*)(sRT + bl * 60);
        float4 rr[15];
#pragma unroll
        for (int q = 0; q < 15; q++) rr[q] = rtp[q];

        float* cRow = sC + bl * 132;
#pragma unroll
        for (int i = 0; i < 16; i++) {
            int vl = half * 16 + i;
            float4 wv0 = *(const float4*)(sWVT + vl * 8);       // w0..w3 (broadcast)
            float4 wv1 = *(const float4*)(sWVT + vl * 8 + 4);   // w4, vtx, vty, vtz
            float4 cv  = *(const float4*)(cRow + vl * 4);

            float4 T0, T1, T2;
#define BLEND(T, i0)                                                              \
            T.x = fmaf(wv0.x, rr[i0].x, fmaf(wv0.y, rr[i0+3].x, fmaf(wv0.z, rr[i0+6].x, \
                  fmaf(wv0.w, rr[i0+9].x, wv1.x * rr[i0+12].x))));               \
            T.y = fmaf(wv0.x, rr[i0].y, fmaf(wv0.y, rr[i0+3].y, fmaf(wv0.z, rr[i0+6].y, \
                  fmaf(wv0.w, rr[i0+9].y, wv1.x * rr[i0+12].y))));               \
            T.z = fmaf(wv0.x, rr[i0].z, fmaf(wv0.y, rr[i0+3].z, fmaf(wv0.z, rr[i0+6].z, \
                  fmaf(wv0.w, rr[i0+9].z, wv1.x * rr[i0+12].z))));               \
            T.w = fmaf(wv0.x, rr[i0].w, fmaf(wv0.y, rr[i0+3].w, fmaf(wv0.z, rr[i0+6].w, \
                  fmaf(wv0.w, rr[i0+9].w, wv1.x * rr[i0+12].w))));
            BLEND(T0, 0) BLEND(T1, 1) BLEND(T2, 2)
#undef BLEND
            float px = cv.x + wv1.y;
            float py = cv.y + wv1.z;
            float pz = cv.z + wv1.w;
            float ox = fmaf(T0.x, px, fmaf(T0.y, py, fmaf(T0.z, pz, T0.w)));
            float oy = fmaf(T1.x, px, fmaf(T1.y, py, fmaf(T1.z, pz, T1.w)));
            float oz = fmaf(T2.x, px, fmaf(T2.y, py, fmaf(T2.z, pz, T2.w)));
            *(float4*)(cRow + vl * 4) = make_float4(ox, oy, oz, 0.f);
        }
    }
    __syncthreads();

    // --- coalesced store sweep: 128 bl x 32 v x 3 floats ---
    for (int i = tid; i < 128 * 96; i += 256) {
        int bl = i / 96, f = i - bl * 96;
        int vv = f / 3, cc = f - vv * 3;
        int v = v0 + vv;
        if (v < VNUM)
            out[((size_t)(b0 + bl) * VNUM + v) * 3 + cc] = sC[bl * 132 + vv * 4 + cc];
    }
}

// ============================================================
// Launch 5 — kernD: landmark gather
// ============================================================
__global__ void kernD(const int* __restrict__ land, const float* __restrict__ verts,
                      float* __restrict__ lmk)
{
    int i = blockIdx.x * blockDim.x + threadIdx.x;
    if (i >= NB * NLMK) return;
    int b = i / NLMK, k = i % NLMK;
    int v = land[k];
    size_t src = ((size_t)b * VNUM + v) * 3;
    size_t dst = (size_t)i * 3;
    lmk[dst + 0] = verts[src + 0];
    lmk[dst + 1] = verts[src + 1];
    lmk[dst + 2] = verts[src + 2];
}

// ============================================================
extern "C" void kernel_launch(void* const* d_in, const int* in_sizes, int n_in,
                              void* d_out, int out_size)
{
    const float* shape = (const float*)d_in[0];
    const float* expr  = (const float*)d_in[1];
    const float* pose  = (const float*)d_in[2];
    const int*   land  = (const int*)  d_in[3];
    const float* vt    = (const float*)d_in[4];
    const float* sd    = (const float*)d_in[5];
    const float* pd    = (const float*)d_in[6];
    const float* Jreg  = (const float*)d_in[7];
    const float* lw    = (const float*)d_in[8];
    const float* eye   = (const float*)d_in[9];
    const float* neck  = (const float*)d_in[10];
    float* out = (float*)d_out;

    cudaFuncSetAttribute(kernG, cudaFuncAttributeMaxDynamicSharedMemorySize, SM_TOT);

    kernF1<<<F1_BLK, 256>>>(sd, vt, pd, Jreg);            // launch 1
    dim3 ga(NJ, 4);
    kernA2<<<ga, 128>>>();                                // launch 2
    kernB<<<NB / 32, 32>>>(shape, expr, pose, eye, neck); // launch 3
    dim3 gg(NPAD4 / 128, NB / 128);
    kernG<<<gg, 256, SM_TOT>>>(vt, lw, out);              // launch 4  <- profiled
    float* lmk = out + (size_t)NB * VNUM * 3;
    kernD<<<(NB * NLMK + 255) / 256, 256>>>(land, out, lmk);  // launch 5
}

// round 8
// speedup vs baseline: 1.0268x; 1.0268x over previous
#include <cuda_runtime.h>
#include <cuda_bf16.h>
#include <math.h>
#include <stdint.h>

#define VNUM   5023
#define NJ     5
#define NB     1024
#define NSHAPE 100
#define NEXPR  50
#define NBETA  150
#define NLMK   68
#define NPOSE  36
#define JR_COLS 453
#define PD_N   (VNUM * 3)      // 15069

#define KP    192              // padded K: 150 betas + 36 pose feats + 6 zero
#define NPAD4 20096            // 157 * 128 >= 4*VNUM

#define VB      20             // vertices per F1 block
#define F1_BLK  252            // 252*20 = 5040 >= 5024

// ---- device scratch ----
__device__ float g_Jr[NJ * JR_COLS];
__device__ float g_relT[NB * NJ * 12];
__device__ __nv_bfloat16 g_A[NB * KP];                // 0.4 MB
__device__ __nv_bfloat16 g_B4[(size_t)NPAD4 * KP];    // 7.7 MB

__device__ __forceinline__ uint32_t smem_u32(const void* p) {
    uint32_t a;
    asm("{ .reg .u64 t; cvta.to.shared.u64 t, %1; cvt.u32.u64 %0, t; }" : "=r"(a) : "l"(p));
    return a;
}

#define LDSM4(R0, R1, R2, R3, ADDR) \
    asm volatile("ldmatrix.sync.aligned.m8n8.x4.shared.b16 {%0,%1,%2,%3}, [%4];" \
        : "=r"(R0), "=r"(R1), "=r"(R2), "=r"(R3) : "r"(ADDR))

#define MMA16816(C, A0, A1, A2, A3, B0, B1) \
    asm volatile("mma.sync.aligned.m16n8k16.row.col.f32.bf16.bf16.f32 " \
        "{%0,%1,%2,%3},{%4,%5,%6,%7},{%8,%9},{%0,%1,%2,%3};" \
        : "+f"((C)[0]), "+f"((C)[1]), "+f"((C)[2]), "+f"((C)[3]) \
        : "r"(A0), "r"(A1), "r"(A2), "r"(A3), "r"(B0), "r"(B1))

#define CP_ASYNC16(DST, SRC) \
    asm volatile("cp.async.cg.shared.global [%0], [%1], 16;" :: "r"(DST), "l"(SRC))
#define CP_ASYNC_WAIT() \
    asm volatile("cp.async.commit_group;\n\tcp.async.wait_group 0;" ::: "memory")

// ============================================================
// Launch 1 — kernZ: zero g_Jr (F1 accumulates atomically into it)
// ============================================================
__global__ void kernZ()
{
    for (int i = threadIdx.x; i < NJ * JR_COLS; i += blockDim.x) g_Jr[i] = 0.f;
}

// ============================================================
// Launch 2 — kernF1: fused B4 build + Jr accumulation (atomics).
// 252 blocks x 256 threads; each block owns 20 vertices, processed
// in 2 sub-chunks of 10 (sd rows staged in smem once, used twice).
// ============================================================
__global__ void __launch_bounds__(256) kernF1(
    const float* __restrict__ sd, const float* __restrict__ vt,
    const float* __restrict__ pd, const float* __restrict__ Jreg)
{
    __shared__ float s_sd[10][456];    // 10 rows x (450 sd | 3 vt | pad)
    __shared__ float s_jr[NJ][VB];
    int tid = threadIdx.x;
    int v0 = blockIdx.x * VB;

    for (int i = tid; i < NJ * VB; i += 256) {
        int j = i / VB, vv = i % VB;
        int v = v0 + vv;
        s_jr[j][vv] = (v < VNUM) ? Jreg[j * VNUM + v] : 0.f;
    }

    float acc[10];
#pragma unroll
    for (int q = 0; q < 10; q++) acc[q] = 0.f;
    int col0 = tid, col1 = tid + 256;

    for (int sub = 0; sub < 2; sub++) {
        __syncthreads();
        int vbase = v0 + sub * 10;
        // stage 10 sd rows (+vt) coalesced
        for (int i = tid; i < 10 * 456; i += 256) {
            int r = i / 456, c = i - r * 456;
            int v = vbase + r;
            float val = 0.f;
            if (v < VNUM) {
                if (c < 450)      val = sd[v * 450 + c];
                else if (c < 453) val = vt[v * 3 + (c - 450)];
            }
            s_sd[r][c] = val;
        }
        __syncthreads();

        // Jr partial accumulation
#pragma unroll
        for (int r = 0; r < 10; r++) {
            int vv = sub * 10 + r;
            float j0 = s_jr[0][vv], j1 = s_jr[1][vv], j2 = s_jr[2][vv];
            float j3 = s_jr[3][vv], j4 = s_jr[4][vv];
            float x0 = s_sd[r][col0];
            acc[0] = fmaf(j0, x0, acc[0]); acc[1] = fmaf(j1, x0, acc[1]);
            acc[2] = fmaf(j2, x0, acc[2]); acc[3] = fmaf(j3, x0, acc[3]);
            acc[4] = fmaf(j4, x0, acc[4]);
            if (col1 < JR_COLS) {
                float x1 = s_sd[r][col1];
                acc[5] = fmaf(j0, x1, acc[5]); acc[6] = fmaf(j1, x1, acc[6]);
                acc[7] = fmaf(j2, x1, acc[7]); acc[8] = fmaf(j3, x1, acc[8]);
                acc[9] = fmaf(j4, x1, acc[9]);
            }
        }

        // B4 rows for these 10 vertices (40 rows x 192)
        for (int i = tid; i < 40 * KP; i += 256) {
            int nl = i / KP, k = i - nl * KP;
            int n = vbase * 4 + nl;
            if (n < NPAD4) {
                int vl2 = nl >> 2, c = nl & 3;
                int v = vbase + vl2;
                float val = 0.f;
                if (v < VNUM && c < 3) {
                    if (k < NBETA)              val = s_sd[vl2][c * NBETA + k];
                    else if (k < NBETA + NPOSE) val = pd[(size_t)(k - NBETA) * PD_N + (v * 3 + c)];
                }
                g_B4[(size_t)n * KP + k] = __float2bfloat16(val);
            }
        }
    }

#pragma unroll
    for (int j = 0; j < NJ; j++) {
        atomicAdd(&g_Jr[j * JR_COLS + col0], acc[j]);
        if (col1 < JR_COLS) atomicAdd(&g_Jr[j * JR_COLS + col1], acc[5 + j]);
    }
}

// ============================================================
// Launch 3 — kernB: joints, Rodrigues, chain -> g_relT + bf16 A rows.
// 32 blocks x 32 threads (1 batch/thread).
// ============================================================
#define BP 153

__global__ void __launch_bounds__(32) kernB(
    const float* __restrict__ shape, const float* __restrict__ expr,
    const float* __restrict__ pose, const float* __restrict__ eye,
    const float* __restrict__ neck)
{
    __shared__ float s_jr[NJ * JR_COLS];
    __shared__ float s_beta[32 * BP];
    int tid = threadIdx.x;
    int b0 = blockIdx.x * 32;

    for (int i = tid; i < NJ * JR_COLS; i += 32) s_jr[i] = g_Jr[i];
    for (int i = tid; i < 32 * NSHAPE; i += 32)
        s_beta[(i / NSHAPE) * BP + (i % NSHAPE)] = shape[b0 * NSHAPE + i];
    for (int i = tid; i < 32 * NEXPR; i += 32)
        s_beta[(i / NEXPR) * BP + NSHAPE + (i % NEXPR)] = expr[b0 * NEXPR + i];
    __syncthreads();

    int b = b0 + tid;
    const float* myb = s_beta + tid * BP;

    float J[NJ][3];
#pragma unroll
    for (int j = 0; j < NJ; j++)
#pragma unroll
        for (int c = 0; c < 3; c++) J[j][c] = s_jr[j * JR_COLS + 450 + c];

    for (int l = 0; l < NBETA; l++) {
        float blv = myb[l];
#pragma unroll
        for (int j = 0; j < NJ; j++)
#pragma unroll
            for (int c = 0; c < 3; c++) J[j][c] = fmaf(s_jr[j * JR_COLS + l], blv, J[j][c]);
    }

    float fp[15];
    fp[0] = pose[b * 6 + 0]; fp[1] = pose[b * 6 + 1]; fp[2] = pose[b * 6 + 2];
    fp[3] = neck[0]; fp[4] = neck[1]; fp[5] = neck[2];
    fp[6] = pose[b * 6 + 3]; fp[7] = pose[b * 6 + 4]; fp[8] = pose[b * 6 + 5];
#pragma unroll
    for (int k = 0; k < 6; k++) fp[9 + k] = eye[k];

    float R[NJ][9];
#pragma unroll
    for (int j = 0; j < NJ; j++) {
        float x = fp[j * 3 + 0], y = fp[j * 3 + 1], z = fp[j * 3 + 2];
        float xa = x + 1e-8f, ya = y + 1e-8f, za = z + 1e-8f;
        float ang = sqrtf(xa * xa + ya * ya + za * za);
        float inv = 1.f / ang;
        float rx = x * inv, ry = y * inv, rz = z * inv;
        float s, c;
        sincosf(ang, &s, &c);
        float t = 1.f - c;
        R[j][0] = 1.f - t * (ry * ry + rz * rz);
        R[j][1] = -s * rz + t * rx * ry;
        R[j][2] =  s * ry + t * rx * rz;
        R[j][3] =  s * rz + t * rx * ry;
        R[j][4] = 1.f - t * (rx * rx + rz * rz);
        R[j][5] = -s * rx + t * ry * rz;
        R[j][6] = -s * ry + t * rx * rz;
        R[j][7] =  s * rx + t * ry * rz;
        R[j][8] = 1.f - t * (rx * rx + ry * ry);
    }

    // --- g_A row: [betas(150) | pose_feature(36) | 0 pad(6)] bf16 ---
    {
        __nv_bfloat16* arow = g_A + (size_t)b * KP;
#pragma unroll 2
        for (int l = 0; l < NBETA; l++) arow[l] = __float2bfloat16(myb[l]);
#pragma unroll
        for (int j = 1; j < NJ; j++)
#pragma unroll
            for (int k = 0; k < 9; k++) {
                float d = (k == 0 || k == 4 || k == 8) ? 1.f : 0.f;
                arow[NBETA + (j - 1) * 9 + k] = __float2bfloat16(R[j][k] - d);
            }
#pragma unroll
        for (int k = NBETA + NPOSE; k < KP; k++) arow[k] = __float2bfloat16(0.f);
    }

    const int par[NJ] = { -1, 0, 1, 1, 1 };
    float rel[NJ][3];
#pragma unroll
    for (int c = 0; c < 3; c++) rel[0][c] = J[0][c];
#pragma unroll
    for (int j = 1; j < NJ; j++)
#pragma unroll
        for (int c = 0; c < 3; c++) rel[j][c] = J[j][c] - J[par[j]][c];

    float cR[NJ][9], ct[NJ][3];
#pragma unroll
    for (int k = 0; k < 9; k++) cR[0][k] = R[0][k];
#pragma unroll
    for (int c = 0; c < 3; c++) ct[0][c] = rel[0][c];
#pragma unroll
    for (int j = 1; j < NJ; j++) {
        int p = par[j];
#pragma unroll
        for (int r = 0; r < 3; r++) {
#pragma unroll
            for (int c = 0; c < 3; c++)
                cR[j][r * 3 + c] = cR[p][r * 3 + 0] * R[j][0 + c]
                                 + cR[p][r * 3 + 1] * R[j][3 + c]
                                 + cR[p][r * 3 + 2] * R[j][6 + c];
            ct[j][r] = cR[p][r * 3 + 0] * rel[j][0] + cR[p][r * 3 + 1] * rel[j][1]
                     + cR[p][r * 3 + 2] * rel[j][2] + ct[p][r];
        }
    }

#pragma unroll
    for (int j = 0; j < NJ; j++)
#pragma unroll
        for (int r = 0; r < 3; r++) {
            float tr = ct[j][r] - (cR[j][r * 3 + 0] * J[j][0] + cR[j][r * 3 + 1] * J[j][1]
                                 + cR[j][r * 3 + 2] * J[j][2]);
            g_relT[b * 60 + j * 12 + r * 4 + 0] = cR[j][r * 3 + 0];
            g_relT[b * 60 + j * 12 + r * 4 + 1] = cR[j][r * 3 + 1];
            g_relT[b * 60 + j * 12 + r * 4 + 2] = cR[j][r * 3 + 2];
            g_relT[b * 60 + j * 12 + r * 4 + 3] = tr;
        }
}

// ============================================================
// Launch 4 — kernG: C[128b x 64n] = A @ B4^T (mma.sync bf16)
// + fused LBS epilogue + fused landmark gather.
// 256 thr = 8 warps (4b x 2n), warp tile 32b x 32n, 3 CTAs/SM.
// smem mainloop: A@0 (128x400B=51200), B@51200 (64x400B=25600) -> 76800
// epilogue reuse: sC@0 (128x68 f32=34816), relT@34816 (30720B),
//                 wvt@65536 (16x8 f32=512), land@66048 (272)
// Epilogue: 2 threads per batch-row; relT hoisted to registers once;
// 8 vertices per thread; coalesced store sweep; landmark scan.
// ============================================================
#define SMB_OFF 51200
#define SM_TOT  76800

__global__ void __launch_bounds__(256, 3) kernG(
    const float* __restrict__ vt, const float* __restrict__ lw,
    const int* __restrict__ land, float* __restrict__ out)
{
    extern __shared__ char smr[];
    uint32_t sb = smem_u32(smr);
    int tid = threadIdx.x;
    int lane = tid & 31, w = tid >> 5;
    int wm = w & 3, wn = w >> 2;          // 4b x 2n grid, warp tile 32b x 32n
    int n0 = blockIdx.x * 64;
    int b0 = blockIdx.y * 128;
    int v0 = n0 >> 2;                     // 16 vertices per tile

    // --- stage A (128x24 uint4) + B (64x24 uint4) via cp.async, pitch 400B ---
    {
        const uint4* gA4 = (const uint4*)(g_A + (size_t)b0 * KP);
        const uint4* gB4 = (const uint4*)(g_B4 + (size_t)n0 * KP);
        for (int i = tid; i < 128 * 24; i += 256) {
            int row = i / 24, q = i - row * 24;
            CP_ASYNC16(sb + row * 400 + q * 16, gA4 + i);
        }
        for (int i = tid; i < 64 * 24; i += 256) {
            int row = i / 24, q = i - row * 24;
            CP_ASYNC16(sb + SMB_OFF + row * 400 + q * 16, gB4 + i);
        }
        CP_ASYNC_WAIT();
    }
    __syncthreads();

    float acc[2][4][4];
#pragma unroll
    for (int a = 0; a < 2; a++)
#pragma unroll
        for (int j = 0; j < 4; j++)
#pragma unroll
            for (int k = 0; k < 4; k++) acc[a][j][k] = 0.f;

    int lrow = lane & 15;
    uint32_t koff = (uint32_t)((lane >> 4) * 16);
    uint32_t aBase = sb + (wm * 32 + lrow) * 400 + koff;
    uint32_t bBase = sb + SMB_OFF + (wn * 32 + lrow) * 400 + koff;

#pragma unroll
    for (int ks = 0; ks < 12; ks++) {
        uint32_t kb = (uint32_t)ks * 32u;
        uint32_t ra[2][4], rb[2][4];
        LDSM4(ra[0][0], ra[0][1], ra[0][2], ra[0][3], aBase + kb);
        LDSM4(ra[1][0], ra[1][1], ra[1][2], ra[1][3], aBase + 16 * 400 + kb);
        LDSM4(rb[0][0], rb[0][1], rb[0][2], rb[0][3], bBase + kb);
        LDSM4(rb[1][0], rb[1][1], rb[1][2], rb[1][3], bBase + 16 * 400 + kb);
#pragma unroll
        for (int a = 0; a < 2; a++)
#pragma unroll
            for (int jj = 0; jj < 2; jj++) {
                MMA16816(acc[a][jj * 2],     ra[a][0], ra[a][1], ra[a][2], ra[a][3],
                         rb[jj][0], rb[jj][2]);
                MMA16816(acc[a][jj * 2 + 1], ra[a][0], ra[a][1], ra[a][2], ra[a][3],
                         rb[jj][1], rb[jj][3]);
            }
    }

    __syncthreads();   // done reading A/B smem

    // --- write accumulators to sC [128 x 68] f32 ---
    float* sC = (float*)smr;
#pragma unroll
    for (int a = 0; a < 2; a++) {
        int r = wm * 32 + a * 16 + (lane >> 2);
        int cb = wn * 32 + (lane & 3) * 2;
#pragma unroll
        for (int j = 0; j < 4; j++) {
            int c = cb + j * 8;
            sC[r * 68 + c]           = acc[a][j][0];
            sC[r * 68 + c + 1]       = acc[a][j][1];
            sC[(r + 8) * 68 + c]     = acc[a][j][2];
            sC[(r + 8) * 68 + c + 1] = acc[a][j][3];
        }
    }

    // --- stage relT (128x60), packed weights+template (16x8), land ---
    float* sRT = (float*)(smr + 34816);
    for (int i = tid; i < 128 * 60; i += 256) sRT[i] = g_relT[b0 * 60 + i];
    float* sWVT = (float*)(smr + 65536);
    if (tid < 16 * 8) {
        int vl = tid >> 3, q = tid & 7;
        int v = v0 + vl;
        float val = 0.f;
        if (v < VNUM) {
            if (q < 5)      val = lw[v * NJ + q];
            else if (q < 8) val = vt[v * 3 + (q - 5)];
        }
        sWVT[tid] = val;
    }
    int* sLand = (int*)(smr + 66048);
    if (tid < NLMK) sLand[tid] = land[tid];
    __syncthreads();

    // --- epilogue: 2 threads per bl; relT in registers; 8 v each ---
    {
        int bl = tid & 127;
        int half = tid >> 7;
        const float4* rtp = (const float4*)(sRT + bl * 60);
        float4 rr[15];
#pragma unroll
        for (int q = 0; q < 15; q++) rr[q] = rtp[q];

        float* cRow = sC + bl * 68;
#pragma unroll
        for (int i = 0; i < 8; i++) {
            int vl = half * 8 + i;
            float4 wv0 = *(const float4*)(sWVT + vl * 8);       // w0..w3
            float4 wv1 = *(const float4*)(sWVT + vl * 8 + 4);   // w4, vtx, vty, vtz
            float4 cv  = *(const float4*)(cRow + vl * 4);

            float4 T0, T1, T2;
#define BLEND(T, i0)                                                              \
            T.x = fmaf(wv0.x, rr[i0].x, fmaf(wv0.y, rr[i0+3].x, fmaf(wv0.z, rr[i0+6].x, \
                  fmaf(wv0.w, rr[i0+9].x, wv1.x * rr[i0+12].x))));               \
            T.y = fmaf(wv0.x, rr[i0].y, fmaf(wv0.y, rr[i0+3].y, fmaf(wv0.z, rr[i0+6].y, \
                  fmaf(wv0.w, rr[i0+9].y, wv1.x * rr[i0+12].y))));               \
            T.z = fmaf(wv0.x, rr[i0].z, fmaf(wv0.y, rr[i0+3].z, fmaf(wv0.z, rr[i0+6].z, \
                  fmaf(wv0.w, rr[i0+9].z, wv1.x * rr[i0+12].z))));               \
            T.w = fmaf(wv0.x, rr[i0].w, fmaf(wv0.y, rr[i0+3].w, fmaf(wv0.z, rr[i0+6].w, \
                  fmaf(wv0.w, rr[i0+9].w, wv1.x * rr[i0+12].w))));
            BLEND(T0, 0) BLEND(T1, 1) BLEND(T2, 2)
#undef BLEND
            float px = cv.x + wv1.y;
            float py = cv.y + wv1.z;
            float pz = cv.z + wv1.w;
            float ox = fmaf(T0.x, px, fmaf(T0.y, py, fmaf(T0.z, pz, T0.w)));
            float oy = fmaf(T1.x, px, fmaf(T1.y, py, fmaf(T1.z, pz, T1.w)));
            float oz = fmaf(T2.x, px, fmaf(T2.y, py, fmaf(T2.z, pz, T2.w)));
            *(float4*)(cRow + vl * 4) = make_float4(ox, oy, oz, 0.f);
        }
    }
    __syncthreads();

    // --- coalesced store sweep: 128 bl x 16 v x 3 floats ---
    for (int i = tid; i < 128 * 48; i += 256) {
        int bl = i / 48, f = i - bl * 48;
        int vv = f / 3, cc = f - vv * 3;
        int v = v0 + vv;
        if (v < VNUM)
            out[((size_t)(b0 + bl) * VNUM + v) * 3 + cc] = sC[bl * 68 + vv * 4 + cc];
    }

    // --- fused landmark gather: lmk[(b*68+k)*3+c] for land[k] in this tile ---
    {
        float* lmk = out + (size_t)NB * VNUM * 3;
#pragma unroll 4
        for (int k = 0; k < NLMK; k++) {
            int v = sLand[k];
            if (v >= v0 && v < v0 + 16) {
                int vl = v - v0;
                if (tid < 128) {
                    int bl = tid;
                    size_t dst = ((size_t)(b0 + bl) * NLMK + k) * 3;
                    lmk[dst + 0] = sC[bl * 68 + vl * 4 + 0];
                    lmk[dst + 1] = sC[bl * 68 + vl * 4 + 1];
                    lmk[dst + 2] = sC[bl * 68 + vl * 4 + 2];
                }
            }
        }
    }
}

// ============================================================
extern "C" void kernel_launch(void* const* d_in, const int* in_sizes, int n_in,
                              void* d_out, int out_size)
{
    const float* shape = (const float*)d_in[0];
    const float* expr  = (const float*)d_in[1];
    const float* pose  = (const float*)d_in[2];
    const int*   land  = (const int*)  d_in[3];
    const float* vt    = (const float*)d_in[4];
    const float* sd    = (const float*)d_in[5];
    const float* pd    = (const float*)d_in[6];
    const float* Jreg  = (const float*)d_in[7];
    const float* lw    = (const float*)d_in[8];
    const float* eye   = (const float*)d_in[9];
    const float* neck  = (const float*)d_in[10];
    float* out = (float*)d_out;

    cudaFuncSetAttribute(kernG, cudaFuncAttributeMaxDynamicSharedMemorySize, SM_TOT);

    kernZ<<<1, 256>>>();                                  // launch 1
    kernF1<<<F1_BLK, 256>>>(sd, vt, pd, Jreg);            // launch 2
    kernB<<<NB / 32, 32>>>(shape, expr, pose, eye, neck); // launch 3
    dim3 gg(NPAD4 / 64, NB / 128);
    kernG<<<gg, 256, SM_TOT>>>(vt, lw, land, out);        // launch 4  <- profiled
}

// round 9
// speedup vs baseline: 1.2371x; 1.2048x over previous
#include <cuda_runtime.h>
#include <cuda_bf16.h>
#include <math.h>
#include <stdint.h>

#define VNUM   5023
#define NJ     5
#define NB     1024
#define NSHAPE 100
#define NEXPR  50
#define NBETA  150
#define NLMK   68
#define NPOSE  36
#define JR_COLS 453
#define PD_N   (VNUM * 3)      // 15069

#define KP    192              // padded K: 150 betas + 36 pose feats + 6 zero
#define NPAD4 20096            // 157 * 128 >= 4*VNUM

#define VB      20             // vertices per F1 block
#define F1_BLK  252            // 252*20 = 5040 >= 5024

// ---- device scratch ----
__device__ float g_Jr[NJ * JR_COLS];
__device__ float g_relT[NB * NJ * 12];
__device__ __nv_bfloat16 g_A[NB * KP];                // 0.4 MB
__device__ __nv_bfloat16 g_B4[(size_t)NPAD4 * KP];    // 7.7 MB

__device__ __forceinline__ uint32_t smem_u32(const void* p) {
    uint32_t a;
    asm("{ .reg .u64 t; cvta.to.shared.u64 t, %1; cvt.u32.u64 %0, t; }" : "=r"(a) : "l"(p));
    return a;
}

#define LDSM4(R0, R1, R2, R3, ADDR) \
    asm volatile("ldmatrix.sync.aligned.m8n8.x4.shared.b16 {%0,%1,%2,%3}, [%4];" \
        : "=r"(R0), "=r"(R1), "=r"(R2), "=r"(R3) : "r"(ADDR))

#define MMA16816(C, A0, A1, A2, A3, B0, B1) \
    asm volatile("mma.sync.aligned.m16n8k16.row.col.f32.bf16.bf16.f32 " \
        "{%0,%1,%2,%3},{%4,%5,%6,%7},{%8,%9},{%0,%1,%2,%3};" \
        : "+f"((C)[0]), "+f"((C)[1]), "+f"((C)[2]), "+f"((C)[3]) \
        : "r"(A0), "r"(A1), "r"(A2), "r"(A3), "r"(B0), "r"(B1))

#define CP_ASYNC16(DST, SRC) \
    asm volatile("cp.async.cg.shared.global [%0], [%1], 16;" :: "r"(DST), "l"(SRC))
#define CP_ASYNC_WAIT() \
    asm volatile("cp.async.commit_group;\n\tcp.async.wait_group 0;" ::: "memory")

// ============================================================
// Launch 1 — kernZ: zero g_Jr (F1 accumulates atomically into it)
// ============================================================
__global__ void kernZ()
{
    for (int i = threadIdx.x; i < NJ * JR_COLS; i += blockDim.x) g_Jr[i] = 0.f;
}

// ============================================================
// Launch 2 — kernF1: fused B4 build + Jr accumulation (atomics).
// 252 blocks x 256 threads; each block owns 20 vertices in 2 sub-chunks
// of 10.  sd rows staged once (used for Jr AND B4); the posedirs slice
// [36 x 30] is staged with k = warp-row, n = lane (coalesced 120B rows)
// fixing the previous 60KB-strided per-thread pd reads.
// ============================================================
__global__ void __launch_bounds__(256) kernF1(
    const float* __restrict__ sd, const float* __restrict__ vt,
    const float* __restrict__ pd, const float* __restrict__ Jreg)
{
    __shared__ float s_sd[10][456];    // 10 rows x (450 sd | 3 vt | pad)
    __shared__ float s_jr[NJ][VB];
    __shared__ float s_pd[NPOSE][32];  // 36 k-rows x 30 n-values (+pad)
    int tid = threadIdx.x;
    int v0 = blockIdx.x * VB;

    for (int i = tid; i < NJ * VB; i += 256) {
        int j = i / VB, vv = i % VB;
        int v = v0 + vv;
        s_jr[j][vv] = (v < VNUM) ? Jreg[j * VNUM + v] : 0.f;
    }

    float acc[10];
#pragma unroll
    for (int q = 0; q < 10; q++) acc[q] = 0.f;
    int col0 = tid, col1 = tid + 256;

    for (int sub = 0; sub < 2; sub++) {
        __syncthreads();
        int vbase = v0 + sub * 10;
        // stage 10 sd rows (+vt) coalesced
        for (int i = tid; i < 10 * 456; i += 256) {
            int r = i / 456, c = i - r * 456;
            int v = vbase + r;
            float val = 0.f;
            if (v < VNUM) {
                if (c < 450)      val = sd[v * 450 + c];
                else if (c < 453) val = vt[v * 3 + (c - 450)];
            }
            s_sd[r][c] = val;
        }
        // stage pd slice: row k (warp), lane nn -> pd[k*PD_N + vbase*3 + nn]
        for (int i = tid; i < NPOSE * 32; i += 256) {
            int k = i >> 5, nn = i & 31;
            int ng = vbase * 3 + nn;
            s_pd[k][nn] = (nn < 30 && ng < PD_N) ? pd[(size_t)k * PD_N + ng] : 0.f;
        }
        __syncthreads();

        // Jr partial accumulation
#pragma unroll
        for (int r = 0; r < 10; r++) {
            int vv = sub * 10 + r;
            float j0 = s_jr[0][vv], j1 = s_jr[1][vv], j2 = s_jr[2][vv];
            float j3 = s_jr[3][vv], j4 = s_jr[4][vv];
            float x0 = s_sd[r][col0];
            acc[0] = fmaf(j0, x0, acc[0]); acc[1] = fmaf(j1, x0, acc[1]);
            acc[2] = fmaf(j2, x0, acc[2]); acc[3] = fmaf(j3, x0, acc[3]);
            acc[4] = fmaf(j4, x0, acc[4]);
            if (col1 < JR_COLS) {
                float x1 = s_sd[r][col1];
                acc[5] = fmaf(j0, x1, acc[5]); acc[6] = fmaf(j1, x1, acc[6]);
                acc[7] = fmaf(j2, x1, acc[7]); acc[8] = fmaf(j3, x1, acc[8]);
                acc[9] = fmaf(j4, x1, acc[9]);
            }
        }

        // B4 rows for these 10 vertices (40 rows x 192), all from smem
        for (int i = tid; i < 40 * KP; i += 256) {
            int nl = i / KP, k = i - nl * KP;
            int n = vbase * 4 + nl;
            if (n < NPAD4) {
                int vl2 = nl >> 2, c = nl & 3;
                int v = vbase + vl2;
                float val = 0.f;
                if (v < VNUM && c < 3) {
                    if (k < NBETA)              val = s_sd[vl2][c * NBETA + k];
                    else if (k < NBETA + NPOSE) val = s_pd[k - NBETA][vl2 * 3 + c];
                }
                g_B4[(size_t)n * KP + k] = __float2bfloat16(val);
            }
        }
    }

#pragma unroll
    for (int j = 0; j < NJ; j++) {
        atomicAdd(&g_Jr[j * JR_COLS + col0], acc[j]);
        if (col1 < JR_COLS) atomicAdd(&g_Jr[j * JR_COLS + col1], acc[5 + j]);
    }
}

// ============================================================
// Launch 3 — kernB: joints, Rodrigues, chain -> g_relT + bf16 A rows.
// 32 blocks x 32 threads (1 batch/thread).
// ============================================================
#define BP 153

__global__ void __launch_bounds__(32) kernB(
    const float* __restrict__ shape, const float* __restrict__ expr,
    const float* __restrict__ pose, const float* __restrict__ eye,
    const float* __restrict__ neck)
{
    __shared__ float s_jr[NJ * JR_COLS];
    __shared__ float s_beta[32 * BP];
    int tid = threadIdx.x;
    int b0 = blockIdx.x * 32;

    for (int i = tid; i < NJ * JR_COLS; i += 32) s_jr[i] = g_Jr[i];
    for (int i = tid; i < 32 * NSHAPE; i += 32)
        s_beta[(i / NSHAPE) * BP + (i % NSHAPE)] = shape[b0 * NSHAPE + i];
    for (int i = tid; i < 32 * NEXPR; i += 32)
        s_beta[(i / NEXPR) * BP + NSHAPE + (i % NEXPR)] = expr[b0 * NEXPR + i];
    __syncthreads();

    int b = b0 + tid;
    const float* myb = s_beta + tid * BP;

    float J[NJ][3];
#pragma unroll
    for (int j = 0; j < NJ; j++)
#pragma unroll
        for (int c = 0; c < 3; c++) J[j][c] = s_jr[j * JR_COLS + 450 + c];

    for (int l = 0; l < NBETA; l++) {
        float blv = myb[l];
#pragma unroll
        for (int j = 0; j < NJ; j++)
#pragma unroll
            for (int c = 0; c < 3; c++) J[j][c] = fmaf(s_jr[j * JR_COLS + l], blv, J[j][c]);
    }

    float fp[15];
    fp[0] = pose[b * 6 + 0]; fp[1] = pose[b * 6 + 1]; fp[2] = pose[b * 6 + 2];
    fp[3] = neck[0]; fp[4] = neck[1]; fp[5] = neck[2];
    fp[6] = pose[b * 6 + 3]; fp[7] = pose[b * 6 + 4]; fp[8] = pose[b * 6 + 5];
#pragma unroll
    for (int k = 0; k < 6; k++) fp[9 + k] = eye[k];

    float R[NJ][9];
#pragma unroll
    for (int j = 0; j < NJ; j++) {
        float x = fp[j * 3 + 0], y = fp[j * 3 + 1], z = fp[j * 3 + 2];
        float xa = x + 1e-8f, ya = y + 1e-8f, za = z + 1e-8f;
        float ang = sqrtf(xa * xa + ya * ya + za * za);
        float inv = 1.f / ang;
        float rx = x * inv, ry = y * inv, rz = z * inv;
        float s, c;
        sincosf(ang, &s, &c);
        float t = 1.f - c;
        R[j][0] = 1.f - t * (ry * ry + rz * rz);
        R[j][1] = -s * rz + t * rx * ry;
        R[j][2] =  s * ry + t * rx * rz;
        R[j][3] =  s * rz + t * rx * ry;
        R[j][4] = 1.f - t * (rx * rx + rz * rz);
        R[j][5] = -s * rx + t * ry * rz;
        R[j][6] = -s * ry + t * rx * rz;
        R[j][7] =  s * rx + t * ry * rz;
        R[j][8] = 1.f - t * (rx * rx + ry * ry);
    }

    // --- g_A row: [betas(150) | pose_feature(36) | 0 pad(6)] bf16 ---
    {
        __nv_bfloat16* arow = g_A + (size_t)b * KP;
#pragma unroll 2
        for (int l = 0; l < NBETA; l++) arow[l] = __float2bfloat16(myb[l]);
#pragma unroll
        for (int j = 1; j < NJ; j++)
#pragma unroll
            for (int k = 0; k < 9; k++) {
                float d = (k == 0 || k == 4 || k == 8) ? 1.f : 0.f;
                arow[NBETA + (j - 1) * 9 + k] = __float2bfloat16(R[j][k] - d);
            }
#pragma unroll
        for (int k = NBETA + NPOSE; k < KP; k++) arow[k] = __float2bfloat16(0.f);
    }

    const int par[NJ] = { -1, 0, 1, 1, 1 };
    float rel[NJ][3];
#pragma unroll
    for (int c = 0; c < 3; c++) rel[0][c] = J[0][c];
#pragma unroll
    for (int j = 1; j < NJ; j++)
#pragma unroll
        for (int c = 0; c < 3; c++) rel[j][c] = J[j][c] - J[par[j]][c];

    float cR[NJ][9], ct[NJ][3];
#pragma unroll
    for (int k = 0; k < 9; k++) cR[0][k] = R[0][k];
#pragma unroll
    for (int c = 0; c < 3; c++) ct[0][c] = rel[0][c];
#pragma unroll
    for (int j = 1; j < NJ; j++) {
        int p = par[j];
#pragma unroll
        for (int r = 0; r < 3; r++) {
#pragma unroll
            for (int c = 0; c < 3; c++)
                cR[j][r * 3 + c] = cR[p][r * 3 + 0] * R[j][0 + c]
                                 + cR[p][r * 3 + 1] * R[j][3 + c]
                                 + cR[p][r * 3 + 2] * R[j][6 + c];
            ct[j][r] = cR[p][r * 3 + 0] * rel[j][0] + cR[p][r * 3 + 1] * rel[j][1]
                     + cR[p][r * 3 + 2] * rel[j][2] + ct[p][r];
        }
    }

#pragma unroll
    for (int j = 0; j < NJ; j++)
#pragma unroll
        for (int r = 0; r < 3; r++) {
            float tr = ct[j][r] - (cR[j][r * 3 + 0] * J[j][0] + cR[j][r * 3 + 1] * J[j][1]
                                 + cR[j][r * 3 + 2] * J[j][2]);
            g_relT[b * 60 + j * 12 + r * 4 + 0] = cR[j][r * 3 + 0];
            g_relT[b * 60 + j * 12 + r * 4 + 1] = cR[j][r * 3 + 1];
            g_relT[b * 60 + j * 12 + r * 4 + 2] = cR[j][r * 3 + 2];
            g_relT[b * 60 + j * 12 + r * 4 + 3] = tr;
        }
}

// ============================================================
// Launch 4 — kernG: C[128b x 64n] = A @ B4^T (mma.sync bf16)
// + fused LBS epilogue (R6-measured version: 69us).
// 256 thr = 8 warps (4b x 2n), warp tile 32b x 32n, 3 CTAs/SM.
// smem mainloop: A@0 (128x400B=51200), B@51200 (64x400B=25600) -> 76800
// epilogue reuse: sC@0 (128x68 f32=34816), relT@34816 (30720),
//                 w@65536 (320), vt@65856 (192)
// ============================================================
#define SMB_OFF 51200
#define SM_TOT  76800

__global__ void __launch_bounds__(256, 3) kernG(
    const float* __restrict__ vt, const float* __restrict__ lw,
    float* __restrict__ out)
{
    extern __shared__ char smr[];
    uint32_t sb = smem_u32(smr);
    int tid = threadIdx.x;
    int lane = tid & 31, w = tid >> 5;
    int wm = w & 3, wn = w >> 2;          // 4b x 2n grid, warp tile 32b x 32n
    int n0 = blockIdx.x * 64;
    int b0 = blockIdx.y * 128;
    int v0 = n0 >> 2;                     // 16 vertices per tile

    // --- stage A (128x24 uint4) + B (64x24 uint4) via cp.async, pitch 400B ---
    {
        const uint4* gA4 = (const uint4*)(g_A + (size_t)b0 * KP);
        const uint4* gB4 = (const uint4*)(g_B4 + (size_t)n0 * KP);
        for (int i = tid; i < 128 * 24; i += 256) {
            int row = i / 24, q = i - row * 24;
            CP_ASYNC16(sb + row * 400 + q * 16, gA4 + i);
        }
        for (int i = tid; i < 64 * 24; i += 256) {
            int row = i / 24, q = i - row * 24;
            CP_ASYNC16(sb + SMB_OFF + row * 400 + q * 16, gB4 + i);
        }
        CP_ASYNC_WAIT();
    }
    __syncthreads();

    float acc[2][4][4];
#pragma unroll
    for (int a = 0; a < 2; a++)
#pragma unroll
        for (int j = 0; j < 4; j++)
#pragma unroll
            for (int k = 0; k < 4; k++) acc[a][j][k] = 0.f;

    int lrow = lane & 15;
    uint32_t koff = (uint32_t)((lane >> 4) * 16);
    uint32_t aBase = sb + (wm * 32 + lrow) * 400 + koff;
    uint32_t bBase = sb + SMB_OFF + (wn * 32 + lrow) * 400 + koff;

#pragma unroll
    for (int ks = 0; ks < 12; ks++) {
        uint32_t kb = (uint32_t)ks * 32u;
        uint32_t ra[2][4], rb[2][4];
        LDSM4(ra[0][0], ra[0][1], ra[0][2], ra[0][3], aBase + kb);
        LDSM4(ra[1][0], ra[1][1], ra[1][2], ra[1][3], aBase + 16 * 400 + kb);
        LDSM4(rb[0][0], rb[0][1], rb[0][2], rb[0][3], bBase + kb);
        LDSM4(rb[1][0], rb[1][1], rb[1][2], rb[1][3], bBase + 16 * 400 + kb);
#pragma unroll
        for (int a = 0; a < 2; a++)
#pragma unroll
            for (int jj = 0; jj < 2; jj++) {
                MMA16816(acc[a][jj * 2],     ra[a][0], ra[a][1], ra[a][2], ra[a][3],
                         rb[jj][0], rb[jj][2]);
                MMA16816(acc[a][jj * 2 + 1], ra[a][0], ra[a][1], ra[a][2], ra[a][3],
                         rb[jj][1], rb[jj][3]);
            }
    }

    __syncthreads();   // done reading A/B smem

    // --- write accumulators to sC [128 x 68] f32 ---
    float* sC = (float*)smr;
#pragma unroll
    for (int a = 0; a < 2; a++) {
        int r = wm * 32 + a * 16 + (lane >> 2);
        int cb = wn * 32 + (lane & 3) * 2;
#pragma unroll
        for (int j = 0; j < 4; j++) {
            int c = cb + j * 8;
            sC[r * 68 + c]           = acc[a][j][0];
            sC[r * 68 + c + 1]       = acc[a][j][1];
            sC[(r + 8) * 68 + c]     = acc[a][j][2];
            sC[(r + 8) * 68 + c + 1] = acc[a][j][3];
        }
    }

    // --- stage relT / weights / template ---
    float* sRT = (float*)(smr + 34816);
    for (int i = tid; i < 128 * 60; i += 256) sRT[i] = g_relT[b0 * 60 + i];
    float* sW = (float*)(smr + 65536);
    if (tid < 16 * NJ) {
        int vl = tid / NJ;
        int v = v0 + vl;
        sW[tid] = (v < VNUM) ? lw[v * NJ + (tid % NJ)] : 0.f;
    }
    float* sVT = (float*)(smr + 65856);
    if (tid < 48) {
        int vl = tid / 3;
        int v = v0 + vl;
        sVT[tid] = (v < VNUM) ? vt[v * 3 + (tid % 3)] : 0.f;
    }
    __syncthreads();

    // --- per (b, v): blend transform (float4 vectorized), apply, store ---
#pragma unroll 4
    for (int it = 0; it < 8; it++) {
        int p = it * 256 + tid;
        int vl = p & 15, bl = p >> 4;
        int v = v0 + vl;
        float4 cv = *(const float4*)(sC + bl * 68 + vl * 4);
        const float4* rt4 = (const float4*)(sRT + bl * 60);   // 15 float4
        float w0 = sW[vl * NJ + 0], w1 = sW[vl * NJ + 1], w2 = sW[vl * NJ + 2];
        float w3 = sW[vl * NJ + 3], w4 = sW[vl * NJ + 4];
        float4 T4[3];
#pragma unroll
        for (int q = 0; q < 3; q++) {
            float4 r0 = rt4[q], r1 = rt4[3 + q], r2 = rt4[6 + q];
            float4 r3 = rt4[9 + q], r4 = rt4[12 + q];
            T4[q].x = fmaf(w0, r0.x, fmaf(w1, r1.x, fmaf(w2, r2.x, fmaf(w3, r3.x, w4 * r4.x))));
            T4[q].y = fmaf(w0, r0.y, fmaf(w1, r1.y, fmaf(w2, r2.y, fmaf(w3, r3.y, w4 * r4.y))));
            T4[q].z = fmaf(w0, r0.z, fmaf(w1, r1.z, fmaf(w2, r2.z, fmaf(w3, r3.z, w4 * r4.z))));
            T4[q].w = fmaf(w0, r0.w, fmaf(w1, r1.w, fmaf(w2, r2.w, fmaf(w3, r3.w, w4 * r4.w))));
        }
        float px = cv.x + sVT[vl * 3 + 0];
        float py = cv.y + sVT[vl * 3 + 1];
        float pz = cv.z + sVT[vl * 3 + 2];
        float ox = fmaf(T4[0].x, px, fmaf(T4[0].y, py, fmaf(T4[0].z, pz, T4[0].w)));
        float oy = fmaf(T4[1].x, px, fmaf(T4[1].y, py, fmaf(T4[1].z, pz, T4[1].w)));
        float oz = fmaf(T4[2].x, px, fmaf(T4[2].y, py, fmaf(T4[2].z, pz, T4[2].w)));
        if (v < VNUM) {
            size_t base = ((size_t)(b0 + bl) * VNUM + v) * 3;
            out[base + 0] = ox; out[base + 1] = oy; out[base + 2] = oz;
        }
    }
}

// ============================================================
// Launch 5 — kernD: landmark gather
// ============================================================
__global__ void kernD(const int* __restrict__ land, const float* __restrict__ verts,
                      float* __restrict__ lmk)
{
    int i = blockIdx.x * blockDim.x + threadIdx.x;
    if (i >= NB * NLMK) return;
    int b = i / NLMK, k = i % NLMK;
    int v = land[k];
    size_t src = ((size_t)b * VNUM + v) * 3;
    size_t dst = (size_t)i * 3;
    lmk[dst + 0] = verts[src + 0];
    lmk[dst + 1] = verts[src + 1];
    lmk[dst + 2] = verts[src + 2];
}

// ============================================================
extern "C" void kernel_launch(void* const* d_in, const int* in_sizes, int n_in,
                              void* d_out, int out_size)
{
    const float* shape = (const float*)d_in[0];
    const float* expr  = (const float*)d_in[1];
    const float* pose  = (const float*)d_in[2];
    const int*   land  = (const int*)  d_in[3];
    const float* vt    = (const float*)d_in[4];
    const float* sd    = (const float*)d_in[5];
    const float* pd    = (const float*)d_in[6];
    const float* Jreg  = (const float*)d_in[7];
    const float* lw    = (const float*)d_in[8];
    const float* eye   = (const float*)d_in[9];
    const float* neck  = (const float*)d_in[10];
    float* out = (float*)d_out;

    cudaFuncSetAttribute(kernG, cudaFuncAttributeMaxDynamicSharedMemorySize, SM_TOT);

    kernZ<<<1, 256>>>();                                  // launch 1
    kernF1<<<F1_BLK, 256>>>(sd, vt, pd, Jreg);            // launch 2
    kernB<<<NB / 32, 32>>>(shape, expr, pose, eye, neck); // launch 3
    dim3 gg(NPAD4 / 64, NB / 128);
    kernG<<<gg, 256, SM_TOT>>>(vt, lw, out);              // launch 4  <- profiled
    float* lmk = out + (size_t)NB * VNUM * 3;
    kernD<<<(NB * NLMK + 255) / 256, 256>>>(land, out, lmk);  // launch 5
}

// round 10
// speedup vs baseline: 1.3007x; 1.0514x over previous
#include <cuda_runtime.h>
#include <cuda_bf16.h>
#include <math.h>
#include <stdint.h>

#define VNUM   5023
#define NJ     5
#define NB     1024
#define NSHAPE 100
#define NEXPR  50
#define NBETA  150
#define NLMK   68
#define NPOSE  36
#define JR_COLS 453
#define PD_N   (VNUM * 3)      // 15069

#define KP    192              // padded K: 150 betas + 36 pose feats + 6 zero
#define NPAD3 15072            // 157 * 96 >= 3*VNUM = 15069

#define VB      10             // vertices per F1 block
#define F1_BLK  504            // 504*10 = 5040 >= 5023
#define NSLOT   8              // Jr accumulator slots (atomic contention split)

// ---- device scratch ----
__device__ float g_Jr8[NSLOT * NJ * JR_COLS];
__device__ float g_relT[NB * NJ * 12];
__device__ __nv_bfloat16 g_A[NB * KP];                // 0.4 MB
__device__ __nv_bfloat16 g_B3[(size_t)NPAD3 * KP];    // 5.8 MB

__device__ __forceinline__ uint32_t smem_u32(const void* p) {
    uint32_t a;
    asm("{ .reg .u64 t; cvta.to.shared.u64 t, %1; cvt.u32.u64 %0, t; }" : "=r"(a) : "l"(p));
    return a;
}

#define LDSM4(R0, R1, R2, R3, ADDR) \
    asm volatile("ldmatrix.sync.aligned.m8n8.x4.shared.b16 {%0,%1,%2,%3}, [%4];" \
        : "=r"(R0), "=r"(R1), "=r"(R2), "=r"(R3) : "r"(ADDR))

#define MMA16816(C, A0, A1, A2, A3, B0, B1) \
    asm volatile("mma.sync.aligned.m16n8k16.row.col.f32.bf16.bf16.f32 " \
        "{%0,%1,%2,%3},{%4,%5,%6,%7},{%8,%9},{%0,%1,%2,%3};" \
        : "+f"((C)[0]), "+f"((C)[1]), "+f"((C)[2]), "+f"((C)[3]) \
        : "r"(A0), "r"(A1), "r"(A2), "r"(A3), "r"(B0), "r"(B1))

#define CP_ASYNC16(DST, SRC) \
    asm volatile("cp.async.cg.shared.global [%0], [%1], 16;" :: "r"(DST), "l"(SRC))
#define CP_ASYNC_WAIT() \
    asm volatile("cp.async.commit_group;\n\tcp.async.wait_group 0;" ::: "memory")

// ============================================================
// Launch 1 — kernZ: zero the 8 Jr accumulator slots
// ============================================================
__global__ void kernZ()
{
    int base = blockIdx.x * NJ * JR_COLS;
    for (int i = threadIdx.x; i < NJ * JR_COLS; i += blockDim.x)
        g_Jr8[base + i] = 0.f;
}

// ============================================================
// Launch 2 — kernF1: fused B3 build + Jr accumulation.
// 504 blocks x 256 threads; each block owns 10 vertices.
// sd rows staged once (used for Jr AND B3); pd slice staged coalesced.
// B3 stores packed as bf16x2 (STG.32). Atomics into slot blockIdx&7.
// ============================================================
__global__ void __launch_bounds__(256) kernF1(
    const float* __restrict__ sd, const float* __restrict__ vt,
    const float* __restrict__ pd, const float* __restrict__ Jreg)
{
    __shared__ float s_sd[VB][456];    // 10 rows x (450 sd | 3 vt | pad)
    __shared__ float s_jr[NJ][VB];
    __shared__ float s_pd[NPOSE][32];  // 36 k-rows x 30 n-values (+pad)
    int tid = threadIdx.x;
    int v0 = blockIdx.x * VB;
    int slot = blockIdx.x & (NSLOT - 1);

    for (int i = tid; i < NJ * VB; i += 256) {
        int j = i / VB, vv = i % VB;
        int v = v0 + vv;
        s_jr[j][vv] = (v < VNUM) ? Jreg[j * VNUM + v] : 0.f;
    }
    // stage 10 sd rows (+vt) coalesced
    for (int i = tid; i < VB * 456; i += 256) {
        int r = i / 456, c = i - r * 456;
        int v = v0 + r;
        float val = 0.f;
        if (v < VNUM) {
            if (c < 450)      val = sd[v * 450 + c];
            else if (c < 453) val = vt[v * 3 + (c - 450)];
        }
        s_sd[r][c] = val;
    }
    // stage pd slice: row k, lane nn -> pd[k*PD_N + v0*3 + nn]  (coalesced)
    for (int i = tid; i < NPOSE * 32; i += 256) {
        int k = i >> 5, nn = i & 31;
        int ng = v0 * 3 + nn;
        s_pd[k][nn] = (nn < 30 && ng < PD_N) ? pd[(size_t)k * PD_N + ng] : 0.f;
    }
    __syncthreads();

    // --- Jr accumulation ---
    int col0 = tid, col1 = tid + 256;
    float acc[10];
#pragma unroll
    for (int q = 0; q < 10; q++) acc[q] = 0.f;
#pragma unroll
    for (int r = 0; r < VB; r++) {
        float j0 = s_jr[0][r], j1 = s_jr[1][r], j2 = s_jr[2][r];
        float j3 = s_jr[3][r], j4 = s_jr[4][r];
        float x0 = s_sd[r][col0];
        acc[0] = fmaf(j0, x0, acc[0]); acc[1] = fmaf(j1, x0, acc[1]);
        acc[2] = fmaf(j2, x0, acc[2]); acc[3] = fmaf(j3, x0, acc[3]);
        acc[4] = fmaf(j4, x0, acc[4]);
        if (col1 < JR_COLS) {
            float x1 = s_sd[r][col1];
            acc[5] = fmaf(j0, x1, acc[5]); acc[6] = fmaf(j1, x1, acc[6]);
            acc[7] = fmaf(j2, x1, acc[7]); acc[8] = fmaf(j3, x1, acc[8]);
            acc[9] = fmaf(j4, x1, acc[9]);
        }
    }

    // --- B3 build: 30 rows x 96 bf16x2 (packed STG.32) ---
    for (int i = tid; i < 30 * 96; i += 256) {
        int nl = i / 96;
        int kk = (i - nl * 96) * 2;
        int n = v0 * 3 + nl;
        if (n < NPAD3) {
            int vl2 = nl / 3, c = nl - vl2 * 3;
            float f0 = 0.f, f1 = 0.f;
            if (kk < NBETA) {
                f0 = s_sd[vl2][c * NBETA + kk];
                f1 = s_sd[vl2][c * NBETA + kk + 1];
            } else if (kk < NBETA + NPOSE) {
                f0 = s_pd[kk - NBETA][nl];
                f1 = (kk + 1 < NBETA + NPOSE) ? s_pd[kk + 1 - NBETA][nl] : 0.f;
            }
            __nv_bfloat162 pk;
            pk.x = __float2bfloat16(f0);
            pk.y = __float2bfloat16(f1);
            *(__nv_bfloat162*)(g_B3 + (size_t)n * KP + kk) = pk;
        }
    }

    // --- atomics into slot (63 CTAs per address) ---
    float* jr = g_Jr8 + slot * NJ * JR_COLS;
#pragma unroll
    for (int j = 0; j < NJ; j++) {
        atomicAdd(&jr[j * JR_COLS + col0], acc[j]);
        if (col1 < JR_COLS) atomicAdd(&jr[j * JR_COLS + col1], acc[5 + j]);
    }
}

// ============================================================
// Launch 3 — kernB: joints, Rodrigues, chain -> g_relT + bf16 A rows.
// 32 blocks x 32 threads (1 batch/thread).  Sums the 8 Jr slots.
// ============================================================
#define BP 153

__global__ void __launch_bounds__(32) kernB(
    const float* __restrict__ shape, const float* __restrict__ expr,
    const float* __restrict__ pose, const float* __restrict__ eye,
    const float* __restrict__ neck)
{
    __shared__ float s_jr[NJ * JR_COLS];
    __shared__ float s_beta[32 * BP];
    int tid = threadIdx.x;
    int b0 = blockIdx.x * 32;

    for (int i = tid; i < NJ * JR_COLS; i += 32) {
        float s = 0.f;
#pragma unroll
        for (int t = 0; t < NSLOT; t++) s += g_Jr8[t * NJ * JR_COLS + i];
        s_jr[i] = s;
    }
    for (int i = tid; i < 32 * NSHAPE; i += 32)
        s_beta[(i / NSHAPE) * BP + (i % NSHAPE)] = shape[b0 * NSHAPE + i];
    for (int i = tid; i < 32 * NEXPR; i += 32)
        s_beta[(i / NEXPR) * BP + NSHAPE + (i % NEXPR)] = expr[b0 * NEXPR + i];
    __syncthreads();

    int b = b0 + tid;
    const float* myb = s_beta + tid * BP;

    float J[NJ][3];
#pragma unroll
    for (int j = 0; j < NJ; j++)
#pragma unroll
        for (int c = 0; c < 3; c++) J[j][c] = s_jr[j * JR_COLS + 450 + c];

    for (int l = 0; l < NBETA; l++) {
        float blv = myb[l];
#pragma unroll
        for (int j = 0; j < NJ; j++)
#pragma unroll
            for (int c = 0; c < 3; c++) J[j][c] = fmaf(s_jr[j * JR_COLS + l], blv, J[j][c]);
    }

    float fp[15];
    fp[0] = pose[b * 6 + 0]; fp[1] = pose[b * 6 + 1]; fp[2] = pose[b * 6 + 2];
    fp[3] = neck[0]; fp[4] = neck[1]; fp[5] = neck[2];
    fp[6] = pose[b * 6 + 3]; fp[7] = pose[b * 6 + 4]; fp[8] = pose[b * 6 + 5];
#pragma unroll
    for (int k = 0; k < 6; k++) fp[9 + k] = eye[k];

    float R[NJ][9];
#pragma unroll
    for (int j = 0; j < NJ; j++) {
        float x = fp[j * 3 + 0], y = fp[j * 3 + 1], z = fp[j * 3 + 2];
        float xa = x + 1e-8f, ya = y + 1e-8f, za = z + 1e-8f;
        float ang = sqrtf(xa * xa + ya * ya + za * za);
        float inv = 1.f / ang;
        float rx = x * inv, ry = y * inv, rz = z * inv;
        float s, c;
        sincosf(ang, &s, &c);
        float t = 1.f - c;
        R[j][0] = 1.f - t * (ry * ry + rz * rz);
        R[j][1] = -s * rz + t * rx * ry;
        R[j][2] =  s * ry + t * rx * rz;
        R[j][3] =  s * rz + t * rx * ry;
        R[j][4] = 1.f - t * (rx * rx + rz * rz);
        R[j][5] = -s * rx + t * ry * rz;
        R[j][6] = -s * ry + t * rx * rz;
        R[j][7] =  s * rx + t * ry * rz;
        R[j][8] = 1.f - t * (rx * rx + ry * ry);
    }

    // --- g_A row: [betas(150) | pose_feature(36) | 0 pad(6)] bf16 ---
    {
        __nv_bfloat16* arow = g_A + (size_t)b * KP;
#pragma unroll 2
        for (int l = 0; l < NBETA; l++) arow[l] = __float2bfloat16(myb[l]);
#pragma unroll
        for (int j = 1; j < NJ; j++)
#pragma unroll
            for (int k = 0; k < 9; k++) {
                float d = (k == 0 || k == 4 || k == 8) ? 1.f : 0.f;
                arow[NBETA + (j - 1) * 9 + k] = __float2bfloat16(R[j][k] - d);
            }
#pragma unroll
        for (int k = NBETA + NPOSE; k < KP; k++) arow[k] = __float2bfloat16(0.f);
    }

    const int par[NJ] = { -1, 0, 1, 1, 1 };
    float rel[NJ][3];
#pragma unroll
    for (int c = 0; c < 3; c++) rel[0][c] = J[0][c];
#pragma unroll
    for (int j = 1; j < NJ; j++)
#pragma unroll
        for (int c = 0; c < 3; c++) rel[j][c] = J[j][c] - J[par[j]][c];

    float cR[NJ][9], ct[NJ][3];
#pragma unroll
    for (int k = 0; k < 9; k++) cR[0][k] = R[0][k];
#pragma unroll
    for (int c = 0; c < 3; c++) ct[0][c] = rel[0][c];
#pragma unroll
    for (int j = 1; j < NJ; j++) {
        int p = par[j];
#pragma unroll
        for (int r = 0; r < 3; r++) {
#pragma unroll
            for (int c = 0; c < 3; c++)
                cR[j][r * 3 + c] = cR[p][r * 3 + 0] * R[j][0 + c]
                                 + cR[p][r * 3 + 1] * R[j][3 + c]
                                 + cR[p][r * 3 + 2] * R[j][6 + c];
            ct[j][r] = cR[p][r * 3 + 0] * rel[j][0] + cR[p][r * 3 + 1] * rel[j][1]
                     + cR[p][r * 3 + 2] * rel[j][2] + ct[p][r];
        }
    }

#pragma unroll
    for (int j = 0; j < NJ; j++)
#pragma unroll
        for (int r = 0; r < 3; r++) {
            float tr = ct[j][r] - (cR[j][r * 3 + 0] * J[j][0] + cR[j][r * 3 + 1] * J[j][1]
                                 + cR[j][r * 3 + 2] * J[j][2]);
            g_relT[b * 60 + j * 12 + r * 4 + 0] = cR[j][r * 3 + 0];
            g_relT[b * 60 + j * 12 + r * 4 + 1] = cR[j][r * 3 + 1];
            g_relT[b * 60 + j * 12 + r * 4 + 2] = cR[j][r * 3 + 2];
            g_relT[b * 60 + j * 12 + r * 4 + 3] = tr;
        }
}

// ============================================================
// Launch 4 — kernG: C[64b x 96n] = A @ B3^T (mma.sync bf16)
// + fused LBS epilogue.  Natural n = 3v+c layout (no pad column).
// 256 thr = 8 warps (4m x 2n), warp tile 16b x 48n, 3 CTAs/SM.
// smem mainloop: A@0 (64x400B=25600), B@25600 (96x400B=38400) -> 64000
// epilogue reuse: sC@0 (64x100 f32=25600), relT@25600 (15360),
//                 wvt@40960 (32x9 f32=1152)
// ============================================================
#define SMB_OFF 25600
#define SM_TOT  64000

__global__ void __launch_bounds__(256, 3) kernG(
    const float* __restrict__ vt, const float* __restrict__ lw,
    float* __restrict__ out)
{
    extern __shared__ char smr[];
    uint32_t sb = smem_u32(smr);
    int tid = threadIdx.x;
    int lane = tid & 31, w = tid >> 5;
    int wm = w & 3, wn = w >> 2;          // 4 m-warps x 2 n-warps; warp tile 16x48
    int n0 = blockIdx.x * 96;
    int b0 = blockIdx.y * 64;
    int v0 = blockIdx.x * 32;             // 32 vertices per tile

    // --- stage A (64x24 uint4) + B (96x24 uint4) via cp.async, pitch 400B ---
    {
        const uint4* gA4 = (const uint4*)(g_A + (size_t)b0 * KP);
        const uint4* gB4 = (const uint4*)(g_B3 + (size_t)n0 * KP);
        for (int i = tid; i < 64 * 24; i += 256) {
            int row = i / 24, q = i - row * 24;
            CP_ASYNC16(sb + row * 400 + q * 16, gA4 + i);
        }
        for (int i = tid; i < 96 * 24; i += 256) {
            int row = i / 24, q = i - row * 24;
            CP_ASYNC16(sb + SMB_OFF + row * 400 + q * 16, gB4 + i);
        }
        CP_ASYNC_WAIT();
    }
    __syncthreads();

    float acc[6][4];
#pragma unroll
    for (int j = 0; j < 6; j++)
#pragma unroll
        for (int k = 0; k < 4; k++) acc[j][k] = 0.f;

    int lrow = lane & 15;
    uint32_t koff = (uint32_t)((lane >> 4) * 16);
    uint32_t aBase = sb + (wm * 16 + lrow) * 400 + koff;
    uint32_t bBase = sb + SMB_OFF + (wn * 48 + lrow) * 400 + koff;

#pragma unroll
    for (int ks = 0; ks < 12; ks++) {
        uint32_t kb = (uint32_t)ks * 32u;
        uint32_t ra[4], rb[3][4];
        LDSM4(ra[0], ra[1], ra[2], ra[3], aBase + kb);
#pragma unroll
        for (int jj = 0; jj < 3; jj++)
            LDSM4(rb[jj][0], rb[jj][1], rb[jj][2], rb[jj][3], bBase + jj * (16 * 400) + kb);
#pragma unroll
        for (int jj = 0; jj < 3; jj++) {
            MMA16816(acc[jj * 2],     ra[0], ra[1], ra[2], ra[3], rb[jj][0], rb[jj][2]);
            MMA16816(acc[jj * 2 + 1], ra[0], ra[1], ra[2], ra[3], rb[jj][1], rb[jj][3]);
        }
    }

    __syncthreads();   // done reading A/B smem

    // --- write accumulators to sC [64 x 100] f32 ---
    float* sC = (float*)smr;
    {
        int r = wm * 16 + (lane >> 2);
        int cl = (lane & 3) * 2;
#pragma unroll
        for (int j6 = 0; j6 < 6; j6++) {
            int jj = j6 >> 1, h = j6 & 1;
            int c = wn * 48 + jj * 16 + h * 8 + cl;
            sC[r * 100 + c]           = acc[j6][0];
            sC[r * 100 + c + 1]       = acc[j6][1];
            sC[(r + 8) * 100 + c]     = acc[j6][2];
            sC[(r + 8) * 100 + c + 1] = acc[j6][3];
        }
    }

    // --- stage relT (64x60) and packed weights+template (32x9) ---
    float* sRT = (float*)(smr + 25600);
    for (int i = tid; i < 64 * 60; i += 256) sRT[i] = g_relT[b0 * 60 + i];
    float* sWVT = (float*)(smr + 40960);
    for (int i = tid; i < 32 * 9; i += 256) {
        int vl = i / 9, q = i - vl * 9;
        int v = v0 + vl;
        float val = 0.f;
        if (v < VNUM) {
            if (q < 5)      val = lw[v * NJ + q];
            else if (q < 8) val = vt[v * 3 + (q - 5)];
        }
        sWVT[i] = val;
    }
    __syncthreads();

    // --- epilogue: per (b, v); warp-uniform bl; vl = lane ---
#pragma unroll 4
    for (int it = 0; it < 8; it++) {
        int bl = it * 8 + w;              // warp-uniform batch row
        int vl = lane;
        int v = v0 + vl;
        float cx = sC[bl * 100 + vl * 3 + 0];
        float cy = sC[bl * 100 + vl * 3 + 1];
        float cz = sC[bl * 100 + vl * 3 + 2];
        const float4* rt4 = (const float4*)(sRT + bl * 60);   // 15 float4, broadcast
        float w0 = sWVT[vl * 9 + 0], w1 = sWVT[vl * 9 + 1], w2 = sWVT[vl * 9 + 2];
        float w3 = sWVT[vl * 9 + 3], w4 = sWVT[vl * 9 + 4];
        float4 T4[3];
#pragma unroll
        for (int q = 0; q < 3; q++) {
            float4 r0 = rt4[q], r1 = rt4[3 + q], r2 = rt4[6 + q];
            float4 r3 = rt4[9 + q], r4 = rt4[12 + q];
            T4[q].x = fmaf(w0, r0.x, fmaf(w1, r1.x, fmaf(w2, r2.x, fmaf(w3, r3.x, w4 * r4.x))));
            T4[q].y = fmaf(w0, r0.y, fmaf(w1, r1.y, fmaf(w2, r2.y, fmaf(w3, r3.y, w4 * r4.y))));
            T4[q].z = fmaf(w0, r0.z, fmaf(w1, r1.z, fmaf(w2, r2.z, fmaf(w3, r3.z, w4 * r4.z))));
            T4[q].w = fmaf(w0, r0.w, fmaf(w1, r1.w, fmaf(w2, r2.w, fmaf(w3, r3.w, w4 * r4.w))));
        }
        float px = cx + sWVT[vl * 9 + 5];
        float py = cy + sWVT[vl * 9 + 6];
        float pz = cz + sWVT[vl * 9 + 7];
        float ox = fmaf(T4[0].x, px, fmaf(T4[0].y, py, fmaf(T4[0].z, pz, T4[0].w)));
        float oy = fmaf(T4[1].x, px, fmaf(T4[1].y, py, fmaf(T4[1].z, pz, T4[1].w)));
        float oz = fmaf(T4[2].x, px, fmaf(T4[2].y, py, fmaf(T4[2].z, pz, T4[2].w)));
        if (v < VNUM) {
            size_t base = ((size_t)(b0 + bl) * VNUM + v) * 3;
            out[base + 0] = ox; out[base + 1] = oy; out[base + 2] = oz;
        }
    }
}

// ============================================================
// Launch 5 — kernD: landmark gather
// ============================================================
__global__ void kernD(const int* __restrict__ land, const float* __restrict__ verts,
                      float* __restrict__ lmk)
{
    int i = blockIdx.x * blockDim.x + threadIdx.x;
    if (i >= NB * NLMK) return;
    int b = i / NLMK, k = i % NLMK;
    int v = land[k];
    size_t src = ((size_t)b * VNUM + v) * 3;
    size_t dst = (size_t)i * 3;
    lmk[dst + 0] = verts[src + 0];
    lmk[dst + 1] = verts[src + 1];
    lmk[dst + 2] = verts[src + 2];
}

// ============================================================
extern "C" void kernel_launch(void* const* d_in, const int* in_sizes, int n_in,
                              void* d_out, int out_size)
{
    const float* shape = (const float*)d_in[0];
    const float* expr  = (const float*)d_in[1];
    const float* pose  = (const float*)d_in[2];
    const int*   land  = (const int*)  d_in[3];
    const float* vt    = (const float*)d_in[4];
    const float* sd    = (const float*)d_in[5];
    const float* pd    = (const float*)d_in[6];
    const float* Jreg  = (const float*)d_in[7];
    const float* lw    = (const float*)d_in[8];
    const float* eye   = (const float*)d_in[9];
    const float* neck  = (const float*)d_in[10];
    float* out = (float*)d_out;

    cudaFuncSetAttribute(kernG, cudaFuncAttributeMaxDynamicSharedMemorySize, SM_TOT);

    kernZ<<<NSLOT, 256>>>();                              // launch 1
    kernF1<<<F1_BLK, 256>>>(sd, vt, pd, Jreg);            // launch 2
    kernB<<<NB / 32, 32>>>(shape, expr, pose, eye, neck); // launch 3
    dim3 gg(NPAD3 / 96, NB / 64);
    kernG<<<gg, 256, SM_TOT>>>(vt, lw, out);              // launch 4  <- profiled
    float* lmk = out + (size_t)NB * VNUM * 3;
    kernD<<<(NB * NLMK + 255) / 256, 256>>>(land, out, lmk);  // launch 5
}

// round 11
// speedup vs baseline: 1.3396x; 1.0299x over previous
#include <cuda_runtime.h>
#include <cuda_bf16.h>
#include <math.h>
#include <stdint.h>

#define VNUM   5023
#define NJ     5
#define NB     1024
#define NSHAPE 100
#define NEXPR  50
#define NBETA  150
#define NLMK   68
#define NPOSE  36
#define JR_COLS 453
#define PD_N   (VNUM * 3)      // 15069

#define KP    192              // padded K: 150 betas + 36 pose feats + 6 zero
#define NPAD4 20096            // 157 * 128 >= 4*VNUM

#define VB      10             // vertices per F1 block
#define F1_BLK  504            // 504*10 = 5040 >= 5023
#define NSLOT   8              // Jr accumulator slots (atomic contention split)

// ---- device scratch ----
__device__ float g_Jr8[NSLOT * NJ * JR_COLS];
__device__ float g_relT[NB * NJ * 12];
__device__ __nv_bfloat16 g_A[NB * KP];                // 0.4 MB
__device__ __nv_bfloat16 g_B4[(size_t)NPAD4 * KP];    // 7.7 MB

__device__ __forceinline__ uint32_t smem_u32(const void* p) {
    uint32_t a;
    asm("{ .reg .u64 t; cvta.to.shared.u64 t, %1; cvt.u32.u64 %0, t; }" : "=r"(a) : "l"(p));
    return a;
}

#define LDSM4(R0, R1, R2, R3, ADDR) \
    asm volatile("ldmatrix.sync.aligned.m8n8.x4.shared.b16 {%0,%1,%2,%3}, [%4];" \
        : "=r"(R0), "=r"(R1), "=r"(R2), "=r"(R3) : "r"(ADDR))

#define MMA16816(C, A0, A1, A2, A3, B0, B1) \
    asm volatile("mma.sync.aligned.m16n8k16.row.col.f32.bf16.bf16.f32 " \
        "{%0,%1,%2,%3},{%4,%5,%6,%7},{%8,%9},{%0,%1,%2,%3};" \
        : "+f"((C)[0]), "+f"((C)[1]), "+f"((C)[2]), "+f"((C)[3]) \
        : "r"(A0), "r"(A1), "r"(A2), "r"(A3), "r"(B0), "r"(B1))

#define CP_ASYNC16(DST, SRC) \
    asm volatile("cp.async.cg.shared.global [%0], [%1], 16;" :: "r"(DST), "l"(SRC))
#define CP_ASYNC_WAIT() \
    asm volatile("cp.async.commit_group;\n\tcp.async.wait_group 0;" ::: "memory")

// ============================================================
// Launch 1 — kernZ: zero the 8 Jr accumulator slots
// ============================================================
__global__ void kernZ()
{
    int base = blockIdx.x * NJ * JR_COLS;
    for (int i = threadIdx.x; i < NJ * JR_COLS; i += blockDim.x)
        g_Jr8[base + i] = 0.f;
}

// ============================================================
// Launch 2 — kernF1: fused B4 build + Jr accumulation.
// 504 blocks x 256 threads; each block owns 10 vertices.
// sd rows staged once (used for Jr AND B4); pd slice staged coalesced.
// B4 stores packed as bf16x2 (STG.32). Atomics into slot blockIdx&7.
// ============================================================
__global__ void __launch_bounds__(256) kernF1(
    const float* __restrict__ sd, const float* __restrict__ vt,
    const float* __restrict__ pd, const float* __restrict__ Jreg)
{
    __shared__ float s_sd[VB][456];    // 10 rows x (450 sd | 3 vt | pad)
    __shared__ float s_jr[NJ][VB];
    __shared__ float s_pd[NPOSE][32];  // 36 k-rows x 30 n-values (+pad)
    int tid = threadIdx.x;
    int v0 = blockIdx.x * VB;
    int slot = blockIdx.x & (NSLOT - 1);

    for (int i = tid; i < NJ * VB; i += 256) {
        int j = i / VB, vv = i % VB;
        int v = v0 + vv;
        s_jr[j][vv] = (v < VNUM) ? Jreg[j * VNUM + v] : 0.f;
    }
    // stage 10 sd rows (+vt) coalesced; zero beyond VNUM
    for (int i = tid; i < VB * 456; i += 256) {
        int r = i / 456, c = i - r * 456;
        int v = v0 + r;
        float val = 0.f;
        if (v < VNUM) {
            if (c < 450)      val = sd[v * 450 + c];
            else if (c < 453) val = vt[v * 3 + (c - 450)];
        }
        s_sd[r][c] = val;
    }
    // stage pd slice: row k, lane nn -> pd[k*PD_N + v0*3 + nn]  (coalesced)
    for (int i = tid; i < NPOSE * 32; i += 256) {
        int k = i >> 5, nn = i & 31;
        int ng = v0 * 3 + nn;
        s_pd[k][nn] = (nn < 30 && ng < PD_N) ? pd[(size_t)k * PD_N + ng] : 0.f;
    }
    __syncthreads();

    // --- Jr accumulation ---
    int col0 = tid, col1 = tid + 256;
    float acc[10];
#pragma unroll
    for (int q = 0; q < 10; q++) acc[q] = 0.f;
#pragma unroll
    for (int r = 0; r < VB; r++) {
        float j0 = s_jr[0][r], j1 = s_jr[1][r], j2 = s_jr[2][r];
        float j3 = s_jr[3][r], j4 = s_jr[4][r];
        float x0 = s_sd[r][col0];
        acc[0] = fmaf(j0, x0, acc[0]); acc[1] = fmaf(j1, x0, acc[1]);
        acc[2] = fmaf(j2, x0, acc[2]); acc[3] = fmaf(j3, x0, acc[3]);
        acc[4] = fmaf(j4, x0, acc[4]);
        if (col1 < JR_COLS) {
            float x1 = s_sd[r][col1];
            acc[5] = fmaf(j0, x1, acc[5]); acc[6] = fmaf(j1, x1, acc[6]);
            acc[7] = fmaf(j2, x1, acc[7]); acc[8] = fmaf(j3, x1, acc[8]);
            acc[9] = fmaf(j4, x1, acc[9]);
        }
    }

    // --- B4 build: 40 rows (n = 4v+c) x 96 bf16x2 (packed STG.32) ---
    for (int i = tid; i < 40 * 96; i += 256) {
        int nl = i / 96;
        int kk = (i - nl * 96) * 2;
        int n = v0 * 4 + nl;
        if (n < NPAD4) {
            int vl2 = nl >> 2, c = nl & 3;
            float f0 = 0.f, f1 = 0.f;
            if (c < 3) {
                if (kk < NBETA) {
                    f0 = s_sd[vl2][c * NBETA + kk];
                    f1 = s_sd[vl2][c * NBETA + kk + 1];
                } else if (kk < NBETA + NPOSE) {
                    f0 = s_pd[kk - NBETA][vl2 * 3 + c];
                    f1 = (kk + 1 < NBETA + NPOSE) ? s_pd[kk + 1 - NBETA][vl2 * 3 + c] : 0.f;
                }
            }
            __nv_bfloat162 pk;
            pk.x = __float2bfloat16(f0);
            pk.y = __float2bfloat16(f1);
            *(__nv_bfloat162*)(g_B4 + (size_t)n * KP + kk) = pk;
        }
    }

    // --- atomics into slot (63 CTAs per address) ---
    float* jr = g_Jr8 + slot * NJ * JR_COLS;
#pragma unroll
    for (int j = 0; j < NJ; j++) {
        atomicAdd(&jr[j * JR_COLS + col0], acc[j]);
        if (col1 < JR_COLS) atomicAdd(&jr[j * JR_COLS + col1], acc[5 + j]);
    }
}

// ============================================================
// Launch 3 — kernB: joints, Rodrigues, chain -> g_relT + bf16 A rows.
// 32 blocks x 32 threads (1 batch/thread).  Sums the 8 Jr slots.
// ============================================================
#define BP 153

__global__ void __launch_bounds__(32) kernB(
    const float* __restrict__ shape, const float* __restrict__ expr,
    const float* __restrict__ pose, const float* __restrict__ eye,
    const float* __restrict__ neck)
{
    __shared__ float s_jr[NJ * JR_COLS];
    __shared__ float s_beta[32 * BP];
    int tid = threadIdx.x;
    int b0 = blockIdx.x * 32;

    for (int i = tid; i < NJ * JR_COLS; i += 32) {
        float s = 0.f;
#pragma unroll
        for (int t = 0; t < NSLOT; t++) s += g_Jr8[t * NJ * JR_COLS + i];
        s_jr[i] = s;
    }
    for (int i = tid; i < 32 * NSHAPE; i += 32)
        s_beta[(i / NSHAPE) * BP + (i % NSHAPE)] = shape[b0 * NSHAPE + i];
    for (int i = tid; i < 32 * NEXPR; i += 32)
        s_beta[(i / NEXPR) * BP + NSHAPE + (i % NEXPR)] = expr[b0 * NEXPR + i];
    __syncthreads();

    int b = b0 + tid;
    const float* myb = s_beta + tid * BP;

    float J[NJ][3];
#pragma unroll
    for (int j = 0; j < NJ; j++)
#pragma unroll
        for (int c = 0; c < 3; c++) J[j][c] = s_jr[j * JR_COLS + 450 + c];

    for (int l = 0; l < NBETA; l++) {
        float blv = myb[l];
#pragma unroll
        for (int j = 0; j < NJ; j++)
#pragma unroll
            for (int c = 0; c < 3; c++) J[j][c] = fmaf(s_jr[j * JR_COLS + l], blv, J[j][c]);
    }

    float fp[15];
    fp[0] = pose[b * 6 + 0]; fp[1] = pose[b * 6 + 1]; fp[2] = pose[b * 6 + 2];
    fp[3] = neck[0]; fp[4] = neck[1]; fp[5] = neck[2];
    fp[6] = pose[b * 6 + 3]; fp[7] = pose[b * 6 + 4]; fp[8] = pose[b * 6 + 5];
#pragma unroll
    for (int k = 0; k < 6; k++) fp[9 + k] = eye[k];

    float R[NJ][9];
#pragma unroll
    for (int j = 0; j < NJ; j++) {
        float x = fp[j * 3 + 0], y = fp[j * 3 + 1], z = fp[j * 3 + 2];
        float xa = x + 1e-8f, ya = y + 1e-8f, za = z + 1e-8f;
        float ang = sqrtf(xa * xa + ya * ya + za * za);
        float inv = 1.f / ang;
        float rx = x * inv, ry = y * inv, rz = z * inv;
        float s, c;
        sincosf(ang, &s, &c);
        float t = 1.f - c;
        R[j][0] = 1.f - t * (ry * ry + rz * rz);
        R[j][1] = -s * rz + t * rx * ry;
        R[j][2] =  s * ry + t * rx * rz;
        R[j][3] =  s * rz + t * rx * ry;
        R[j][4] = 1.f - t * (rx * rx + rz * rz);
        R[j][5] = -s * rx + t * ry * rz;
        R[j][6] = -s * ry + t * rx * rz;
        R[j][7] =  s * rx + t * ry * rz;
        R[j][8] = 1.f - t * (rx * rx + ry * ry);
    }

    // --- g_A row: [betas(150) | pose_feature(36) | 0 pad(6)] bf16 ---
    {
        __nv_bfloat16* arow = g_A + (size_t)b * KP;
#pragma unroll 2
        for (int l = 0; l < NBETA; l++) arow[l] = __float2bfloat16(myb[l]);
#pragma unroll
        for (int j = 1; j < NJ; j++)
#pragma unroll
            for (int k = 0; k < 9; k++) {
                float d = (k == 0 || k == 4 || k == 8) ? 1.f : 0.f;
                arow[NBETA + (j - 1) * 9 + k] = __float2bfloat16(R[j][k] - d);
            }
#pragma unroll
        for (int k = NBETA + NPOSE; k < KP; k++) arow[k] = __float2bfloat16(0.f);
    }

    const int par[NJ] = { -1, 0, 1, 1, 1 };
    float rel[NJ][3];
#pragma unroll
    for (int c = 0; c < 3; c++) rel[0][c] = J[0][c];
#pragma unroll
    for (int j = 1; j < NJ; j++)
#pragma unroll
        for (int c = 0; c < 3; c++) rel[j][c] = J[j][c] - J[par[j]][c];

    float cR[NJ][9], ct[NJ][3];
#pragma unroll
    for (int k = 0; k < 9; k++) cR[0][k] = R[0][k];
#pragma unroll
    for (int c = 0; c < 3; c++) ct[0][c] = rel[0][c];
#pragma unroll
    for (int j = 1; j < NJ; j++) {
        int p = par[j];
#pragma unroll
        for (int r = 0; r < 3; r++) {
#pragma unroll
            for (int c = 0; c < 3; c++)
                cR[j][r * 3 + c] = cR[p][r * 3 + 0] * R[j][0 + c]
                                 + cR[p][r * 3 + 1] * R[j][3 + c]
                                 + cR[p][r * 3 + 2] * R[j][6 + c];
            ct[j][r] = cR[p][r * 3 + 0] * rel[j][0] + cR[p][r * 3 + 1] * rel[j][1]
                     + cR[p][r * 3 + 2] * rel[j][2] + ct[p][r];
        }
    }

#pragma unroll
    for (int j = 0; j < NJ; j++)
#pragma unroll
        for (int r = 0; r < 3; r++) {
            float tr = ct[j][r] - (cR[j][r * 3 + 0] * J[j][0] + cR[j][r * 3 + 1] * J[j][1]
                                 + cR[j][r * 3 + 2] * J[j][2]);
            g_relT[b * 60 + j * 12 + r * 4 + 0] = cR[j][r * 3 + 0];
            g_relT[b * 60 + j * 12 + r * 4 + 1] = cR[j][r * 3 + 1];
            g_relT[b * 60 + j * 12 + r * 4 + 2] = cR[j][r * 3 + 2];
            g_relT[b * 60 + j * 12 + r * 4 + 3] = tr;
        }
}

// ============================================================
// Launch 4 — kernG: C[128b x 64n] = A @ B4^T (mma.sync bf16)
// + fused LBS epilogue.  (R9-measured version: 69.3us)
// 256 thr = 8 warps (4b x 2n), warp tile 32b x 32n, 3 CTAs/SM.
// smem mainloop: A@0 (128x400B=51200), B@51200 (64x400B=25600) -> 76800
// epilogue reuse: sC@0 (128x68 f32=34816), relT@34816 (30720),
//                 w@65536 (320), vt@65856 (192)
// ============================================================
#define SMB_OFF 51200
#define SM_TOT  76800

__global__ void __launch_bounds__(256, 3) kernG(
    const float* __restrict__ vt, const float* __restrict__ lw,
    float* __restrict__ out)
{
    extern __shared__ char smr[];
    uint32_t sb = smem_u32(smr);
    int tid = threadIdx.x;
    int lane = tid & 31, w = tid >> 5;
    int wm = w & 3, wn = w >> 2;          // 4b x 2n grid, warp tile 32b x 32n
    int n0 = blockIdx.x * 64;
    int b0 = blockIdx.y * 128;
    int v0 = n0 >> 2;                     // 16 vertices per tile

    // --- stage A (128x24 uint4) + B (64x24 uint4) via cp.async, pitch 400B ---
    {
        const uint4* gA4 = (const uint4*)(g_A + (size_t)b0 * KP);
        const uint4* gB4 = (const uint4*)(g_B4 + (size_t)n0 * KP);
        for (int i = tid; i < 128 * 24; i += 256) {
            int row = i / 24, q = i - row * 24;
            CP_ASYNC16(sb + row * 400 + q * 16, gA4 + i);
        }
        for (int i = tid; i < 64 * 24; i += 256) {
            int row = i / 24, q = i - row * 24;
            CP_ASYNC16(sb + SMB_OFF + row * 400 + q * 16, gB4 + i);
        }
        CP_ASYNC_WAIT();
    }
    __syncthreads();

    float acc[2][4][4];
#pragma unroll
    for (int a = 0; a < 2; a++)
#pragma unroll
        for (int j = 0; j < 4; j++)
#pragma unroll
            for (int k = 0; k < 4; k++) acc[a][j][k] = 0.f;

    int lrow = lane & 15;
    uint32_t koff = (uint32_t)((lane >> 4) * 16);
    uint32_t aBase = sb + (wm * 32 + lrow) * 400 + koff;
    uint32_t bBase = sb + SMB_OFF + (wn * 32 + lrow) * 400 + koff;

#pragma unroll
    for (int ks = 0; ks < 12; ks++) {
        uint32_t kb = (uint32_t)ks * 32u;
        uint32_t ra[2][4], rb[2][4];
        LDSM4(ra[0][0], ra[0][1], ra[0][2], ra[0][3], aBase + kb);
        LDSM4(ra[1][0], ra[1][1], ra[1][2], ra[1][3], aBase + 16 * 400 + kb);
        LDSM4(rb[0][0], rb[0][1], rb[0][2], rb[0][3], bBase + kb);
        LDSM4(rb[1][0], rb[1][1], rb[1][2], rb[1][3], bBase + 16 * 400 + kb);
#pragma unroll
        for (int a = 0; a < 2; a++)
#pragma unroll
            for (int jj = 0; jj < 2; jj++) {
                MMA16816(acc[a][jj * 2],     ra[a][0], ra[a][1], ra[a][2], ra[a][3],
                         rb[jj][0], rb[jj][2]);
                MMA16816(acc[a][jj * 2 + 1], ra[a][0], ra[a][1], ra[a][2], ra[a][3],
                         rb[jj][1], rb[jj][3]);
            }
    }

    __syncthreads();   // done reading A/B smem

    // --- write accumulators to sC [128 x 68] f32 ---
    float* sC = (float*)smr;
#pragma unroll
    for (int a = 0; a < 2; a++) {
        int r = wm * 32 + a * 16 + (lane >> 2);
        int cb = wn * 32 + (lane & 3) * 2;
#pragma unroll
        for (int j = 0; j < 4; j++) {
            int c = cb + j * 8;
            sC[r * 68 + c]           = acc[a][j][0];
            sC[r * 68 + c + 1]       = acc[a][j][1];
            sC[(r + 8) * 68 + c]     = acc[a][j][2];
            sC[(r + 8) * 68 + c + 1] = acc[a][j][3];
        }
    }

    // --- stage relT / weights / template ---
    float* sRT = (float*)(smr + 34816);
    for (int i = tid; i < 128 * 60; i += 256) sRT[i] = g_relT[b0 * 60 + i];
    float* sW = (float*)(smr + 65536);
    if (tid < 16 * NJ) {
        int vl = tid / NJ;
        int v = v0 + vl;
        sW[tid] = (v < VNUM) ? lw[v * NJ + (tid % NJ)] : 0.f;
    }
    float* sVT = (float*)(smr + 65856);
    if (tid < 48) {
        int vl = tid / 3;
        int v = v0 + vl;
        sVT[tid] = (v < VNUM) ? vt[v * 3 + (tid % 3)] : 0.f;
    }
    __syncthreads();

    // --- per (b, v): blend transform (float4 vectorized), apply, store ---
#pragma unroll 4
    for (int it = 0; it < 8; it++) {
        int p = it * 256 + tid;
        int vl = p & 15, bl = p >> 4;
        int v = v0 + vl;
        float4 cv = *(const float4*)(sC + bl * 68 + vl * 4);
        const float4* rt4 = (const float4*)(sRT + bl * 60);   // 15 float4
        float w0 = sW[vl * NJ + 0], w1 = sW[vl * NJ + 1], w2 = sW[vl * NJ + 2];
        float w3 = sW[vl * NJ + 3], w4 = sW[vl * NJ + 4];
        float4 T4[3];
#pragma unroll
        for (int q = 0; q < 3; q++) {
            float4 r0 = rt4[q], r1 = rt4[3 + q], r2 = rt4[6 + q];
            float4 r3 = rt4[9 + q], r4 = rt4[12 + q];
            T4[q].x = fmaf(w0, r0.x, fmaf(w1, r1.x, fmaf(w2, r2.x, fmaf(w3, r3.x, w4 * r4.x))));
            T4[q].y = fmaf(w0, r0.y, fmaf(w1, r1.y, fmaf(w2, r2.y, fmaf(w3, r3.y, w4 * r4.y))));
            T4[q].z = fmaf(w0, r0.z, fmaf(w1, r1.z, fmaf(w2, r2.z, fmaf(w3, r3.z, w4 * r4.z))));
            T4[q].w = fmaf(w0, r0.w, fmaf(w1, r1.w, fmaf(w2, r2.w, fmaf(w3, r3.w, w4 * r4.w))));
        }
        float px = cv.x + sVT[vl * 3 + 0];
        float py = cv.y + sVT[vl * 3 + 1];
        float pz = cv.z + sVT[vl * 3 + 2];
        float ox = fmaf(T4[0].x, px, fmaf(T4[0].y, py, fmaf(T4[0].z, pz, T4[0].w)));
        float oy = fmaf(T4[1].x, px, fmaf(T4[1].y, py, fmaf(T4[1].z, pz, T4[1].w)));
        float oz = fmaf(T4[2].x, px, fmaf(T4[2].y, py, fmaf(T4[2].z, pz, T4[2].w)));
        if (v < VNUM) {
            size_t base = ((size_t)(b0 + bl) * VNUM + v) * 3;
            out[base + 0] = ox; out[base + 1] = oy; out[base + 2] = oz;
        }
    }
}

// ============================================================
// Launch 5 — kernD: landmark gather
// ============================================================
__global__ void kernD(const int* __restrict__ land, const float* __restrict__ verts,
                      float* __restrict__ lmk)
{
    int i = blockIdx.x * blockDim.x + threadIdx.x;
    if (i >= NB * NLMK) return;
    int b = i / NLMK, k = i % NLMK;
    int v = land[k];
    size_t src = ((size_t)b * VNUM + v) * 3;
    size_t dst = (size_t)i * 3;
    lmk[dst + 0] = verts[src + 0];
    lmk[dst + 1] = verts[src + 1];
    lmk[dst + 2] = verts[src + 2];
}

// ============================================================
extern "C" void kernel_launch(void* const* d_in, const int* in_sizes, int n_in,
                              void* d_out, int out_size)
{
    const float* shape = (const float*)d_in[0];
    const float* expr  = (const float*)d_in[1];
    const float* pose  = (const float*)d_in[2];
    const int*   land  = (const int*)  d_in[3];
    const float* vt    = (const float*)d_in[4];
    const float* sd    = (const float*)d_in[5];
    const float* pd    = (const float*)d_in[6];
    const float* Jreg  = (const float*)d_in[7];
    const float* lw    = (const float*)d_in[8];
    const float* eye   = (const float*)d_in[9];
    const float* neck  = (const float*)d_in[10];
    float* out = (float*)d_out;

    cudaFuncSetAttribute(kernG, cudaFuncAttributeMaxDynamicSharedMemorySize, SM_TOT);

    kernZ<<<NSLOT, 256>>>();                              // launch 1
    kernF1<<<F1_BLK, 256>>>(sd, vt, pd, Jreg);            // launch 2
    kernB<<<NB / 32, 32>>>(shape, expr, pose, eye, neck); // launch 3
    dim3 gg(NPAD4 / 64, NB / 128);
    kernG<<<gg, 256, SM_TOT>>>(vt, lw, out);              // launch 4  <- profiled
    float* lmk = out + (size_t)NB * VNUM * 3;
    kernD<<<(NB * NLMK + 255) / 256, 256>>>(land, out, lmk);  // launch 5
}